// round 4
// baseline (speedup 1.0000x reference)
#include <cuda_runtime.h>
#include <cuda_bf16.h>
#include <math.h>
#include <stdint.h>

#define NN 40000
#define CC 128
#define HH 4
#define EE 200000
#define TS (1u<<19)
#define TMASK (TS-1u)

#define MT 128
#define NBLK ((NN + MT - 1) / MT)        // 313
#define PITCH 68
#define PLANE (128*PITCH)                // 8704 words
#define AHI 0
#define ALO PLANE
#define B0HI (2*PLANE)
#define B0LO (3*PLANE)
#define B1HI (4*PLANE)
#define B1LO (5*PLANE)
#define RED0 (4*PLANE)                   // k_out only (reuses B1 space)
#define QKV_SMEMB (6*PLANE*4)            // 208896 B
#define OUT_SMEMB ((4*PLANE+512)*4)      // 141312 B

// ---------------- scratch (device globals) ----------------
__device__ float g_Qu[NN*CC], g_Ku[NN*CC], g_Vu[NN*CC];
__device__ float g_Qi[NN*CC], g_Ki[NN*CC], g_Vi[NN*CC];
__device__ float g_agg_u[NN*CC], g_agg_i[NN*CC];
__device__ float g_z_u[NN*HH], g_z_i[NN*HH];
__device__ uint32_t g_Whi[4][CC*CC/2], g_Wlo[4][CC*CC/2];   // q,k,v,o  [128][64] words
__device__ int g_ck_ui[TS], g_cv_ui[TS];
__device__ int g_ck_iu[TS], g_cv_iu[TS];
__device__ int g_rk_ui[TS], g_rk_iu[TS];
__device__ int g_deg_u[NN], g_deg_i[NN], g_indeg_u[NN], g_indeg_i[NN];

// ---------------- helpers ----------------
__device__ __forceinline__ uint32_t smem_u32(const void* p){
  uint32_t a;
  asm("{ .reg .u64 t; cvta.to.shared.u64 t, %1; cvt.u32.u64 %0, t; }" : "=r"(a) : "l"(p));
  return a;
}
__device__ __forceinline__ void bsplit(float a, float b, uint32_t& hi, uint32_t& lo){
  __nv_bfloat16 ha = __float2bfloat16(a), hb = __float2bfloat16(b);
  float ra = a - __bfloat162float(ha);
  float rb = b - __bfloat162float(hb);
  __nv_bfloat16 la = __float2bfloat16(ra), lb = __float2bfloat16(rb);
  hi = ((uint32_t)__bfloat16_as_ushort(hb) << 16) | (uint32_t)__bfloat16_as_ushort(ha);
  lo = ((uint32_t)__bfloat16_as_ushort(lb) << 16) | (uint32_t)__bfloat16_as_ushort(la);
}
__device__ __forceinline__ void mma_bf16(float* c,
    uint32_t a0, uint32_t a1, uint32_t a2, uint32_t a3,
    uint32_t b0, uint32_t b1){
  asm volatile("mma.sync.aligned.m16n8k16.row.col.f32.bf16.bf16.f32 "
    "{%0,%1,%2,%3}, {%4,%5,%6,%7}, {%8,%9}, {%0,%1,%2,%3};"
    : "+f"(c[0]), "+f"(c[1]), "+f"(c[2]), "+f"(c[3])
    : "r"(a0), "r"(a1), "r"(a2), "r"(a3), "r"(b0), "r"(b1));
}
__device__ __forceinline__ void ldsm4(uint32_t* r, uint32_t addr){
  asm volatile("ldmatrix.sync.aligned.m8n8.x4.shared.b16 {%0,%1,%2,%3}, [%4];"
    : "=r"(r[0]), "=r"(r[1]), "=r"(r[2]), "=r"(r[3]) : "r"(addr));
}
#define CP_ASYNC16(dst, src) asm volatile("cp.async.cg.shared.global [%0], [%1], 16;" :: "r"(dst), "l"(src))
#define CP_COMMIT()  asm volatile("cp.async.commit_group;" ::: "memory")
#define CP_WAIT(n)   asm volatile("cp.async.wait_group %0;" :: "n"(n) : "memory")

// copy 128x64-word plane (row-major) to smem at word base with PITCH
__device__ __forceinline__ void cpb(uint32_t sb, int wbase, const uint32_t* __restrict__ gsrc){
  int tid = threadIdx.x;
  #pragma unroll
  for (int it = 0; it < 8; it++){
    int c = tid + it*256;                 // 16B chunk id, 2048 total
    int row = c >> 4, cw = (c & 15) * 4;
    CP_ASYNC16(sb + (uint32_t)(wbase + row*PITCH + cw)*4, gsrc + row*64 + cw);
  }
}

// core: acc[2][8][4] += A @ B^T using ldmatrix fragments (bf16 3-term split)
__device__ __forceinline__ void mma_core(uint32_t a_hi, uint32_t a_lo,
                                         uint32_t b_hi, uint32_t b_lo,
                                         float acc[2][8][4]){
  #pragma unroll
  for (int s = 0; s < 8; s++){
    uint32_t k2b = s*32;
    uint32_t ah[2][4], al[2][4];
    ldsm4(ah[0], a_hi + k2b);
    ldsm4(ah[1], a_hi + 16*PITCH*4 + k2b);
    ldsm4(al[0], a_lo + k2b);
    ldsm4(al[1], a_lo + 16*PITCH*4 + k2b);
    uint32_t bh[4][4], bl[4][4];
    #pragma unroll
    for (int p = 0; p < 4; p++){
      ldsm4(bh[p], b_hi + (uint32_t)p*16*PITCH*4 + k2b);
      ldsm4(bl[p], b_lo + (uint32_t)p*16*PITCH*4 + k2b);
    }
    #pragma unroll
    for (int p = 0; p < 4; p++)
      #pragma unroll
      for (int e = 0; e < 2; e++){
        int nt = p*2 + e;
        uint32_t b0h = bh[p][e*2], b1h = bh[p][e*2+1];
        uint32_t b0l = bl[p][e*2], b1l = bl[p][e*2+1];
        #pragma unroll
        for (int mt = 0; mt < 2; mt++){
          mma_bf16(acc[mt][nt], ah[mt][0],ah[mt][1],ah[mt][2],ah[mt][3], b0h, b1h);
          mma_bf16(acc[mt][nt], ah[mt][0],ah[mt][1],ah[mt][2],ah[mt][3], b0l, b1l);
          mma_bf16(acc[mt][nt], al[mt][0],al[mt][1],al[mt][2],al[mt][3], b0h, b1h);
        }
      }
  }
}

// ---------------- hash helpers ----------------
__device__ __forceinline__ unsigned hmix(int k){
  unsigned x = (unsigned)k; x *= 2654435761u; x ^= x >> 15; return x & TMASK;
}
__device__ __forceinline__ void hinsert_count(int* keys, int* vals, int key){
  unsigned slot = hmix(key);
  while (true){
    int prev = atomicCAS(&keys[slot], -1, key);
    if (prev == -1 || prev == key){ atomicAdd(&vals[slot], 1); return; }
    slot = (slot + 1) & TMASK;
  }
}
__device__ __forceinline__ void hinsert_set(int* keys, int key){
  unsigned slot = hmix(key);
  while (true){
    int prev = atomicCAS(&keys[slot], -1, key);
    if (prev == -1 || prev == key) return;
    slot = (slot + 1) & TMASK;
  }
}
__device__ __forceinline__ int hcount(const int* __restrict__ keys, const int* __restrict__ vals, int key){
  unsigned slot = hmix(key);
  while (true){
    int k = keys[slot];
    if (k == key) return vals[slot];
    if (k == -1) return 0;
    slot = (slot + 1) & TMASK;
  }
}
__device__ __forceinline__ bool hmember(const int* __restrict__ keys, int key){
  unsigned slot = hmix(key);
  while (true){
    int k = keys[slot];
    if (k == key) return true;
    if (k == -1) return false;
    slot = (slot + 1) & TMASK;
  }
}

// ---------------- init / build / wsplit ----------------
__global__ void k_init(){
  int i = blockIdx.x*blockDim.x + threadIdx.x;
  int stride = gridDim.x*blockDim.x;
  for (int j=i;j<NN*CC;j+=stride){ g_agg_u[j]=0.f; g_agg_i[j]=0.f; }
  for (int j=i;j<(int)TS;j+=stride){
    g_ck_ui[j]=-1; g_ck_iu[j]=-1; g_rk_ui[j]=-1; g_rk_iu[j]=-1;
    g_cv_ui[j]=0;  g_cv_iu[j]=0;
  }
  for (int j=i;j<NN*HH;j+=stride){ g_z_u[j]=0.f; g_z_i[j]=0.f; }
  for (int j=i;j<NN;j+=stride){ g_deg_u[j]=0; g_deg_i[j]=0; g_indeg_u[j]=0; g_indeg_i[j]=0; }
}

__global__ void k_build(const int* __restrict__ eui, const int* __restrict__ eiu){
  int i = blockIdx.x*blockDim.x + threadIdx.x;
  if (i < EE){
    int su = eui[i], du = eui[EE+i];
    hinsert_count(g_ck_ui, g_cv_ui, su*NN + du);
    hinsert_set  (g_rk_iu, du*NN + su);
    atomicAdd(&g_deg_u[su],1); atomicAdd(&g_deg_i[du],1); atomicAdd(&g_indeg_i[du],1);
  } else if (i < 2*EE){
    int j = i - EE;
    int si = eiu[j], di = eiu[EE+j];
    hinsert_count(g_ck_iu, g_cv_iu, si*NN + di);
    hinsert_set  (g_rk_ui, di*NN + si);
    atomicAdd(&g_deg_i[si],1); atomicAdd(&g_deg_u[di],1); atomicAdd(&g_indeg_u[di],1);
  }
}

__global__ void k_wsplit(const float* __restrict__ Wq, const float* __restrict__ Wk,
                         const float* __restrict__ Wv, const float* __restrict__ Wo){
  const float* Ws[4] = {Wq, Wk, Wv, Wo};
  int m = blockIdx.y;
  int i = blockIdx.x*256 + threadIdx.x;    // pair index 0..8191
  float2 v = *(const float2*)(Ws[m] + i*2);
  uint32_t hi, lo; bsplit(v.x, v.y, hi, lo);
  g_Whi[m][i] = hi; g_Wlo[m][i] = lo;
}

// ---------------- fused QKV GEMMs (both node types, double-buffered B) ----------------
__global__ __launch_bounds__(256,1) void k_qkv3(
    const float* __restrict__ Xu, const float* __restrict__ Xi,
    float* __restrict__ Qu, float* __restrict__ Ku, float* __restrict__ Vu,
    float* __restrict__ Qi, float* __restrict__ Ki, float* __restrict__ Vi,
    const float* __restrict__ bq, const float* __restrict__ bk, const float* __restrict__ bv){
  extern __shared__ uint32_t sm[];
  uint32_t sb = smem_u32(sm);
  int tid = threadIdx.x, lane = tid & 31, wid = tid >> 5;
  int mw = wid & 3, nw = wid >> 2, tg = lane >> 2, tq = lane & 3;
  int row0 = blockIdx.x * MT;
  const float* X = blockIdx.y ? Xi : Xu;
  float* Ys[3];
  if (blockIdx.y == 0){ Ys[0]=Qu; Ys[1]=Ku; Ys[2]=Vu; }
  else               { Ys[0]=Qi; Ys[1]=Ki; Ys[2]=Vi; }
  const float* bs[3] = {bq, bk, bv};

  // stage A (inline bf16 split)
  #pragma unroll
  for (int it = 0; it < 32; it++){
    int idx = tid + it*256;
    int row = idx >> 6, j = idx & 63;
    int gr = row0 + row;
    float2 v = make_float2(0.f, 0.f);
    if (gr < NN) v = *(const float2*)(X + (size_t)gr*CC + j*2);
    uint32_t hi, lo; bsplit(v.x, v.y, hi, lo);
    sm[AHI + row*PITCH + j] = hi;
    sm[ALO + row*PITCH + j] = lo;
  }

  // prefetch B0 = Wq planes
  cpb(sb, B0HI, g_Whi[0]); cpb(sb, B0LO, g_Wlo[0]); CP_COMMIT();

  uint32_t a_toff = (uint32_t)(((mw*32 + (lane&15))*PITCH + (lane>>4)*4))*4;
  uint32_t b_toff = (uint32_t)(((nw*64 + (lane&7) + (lane>>4)*8)*PITCH + ((lane>>3)&1)*4))*4;
  uint32_t a_hi = sb + (uint32_t)AHI*4 + a_toff;
  uint32_t a_lo = sb + (uint32_t)ALO*4 + a_toff;

  #pragma unroll
  for (int m = 0; m < 3; m++){
    if (m < 2){
      int wb_hi = ((m+1)&1) ? B1HI : B0HI;
      int wb_lo = ((m+1)&1) ? B1LO : B0LO;
      cpb(sb, wb_hi, g_Whi[m+1]); cpb(sb, wb_lo, g_Wlo[m+1]); CP_COMMIT();
      CP_WAIT(1);
    } else {
      CP_WAIT(0);
    }
    __syncthreads();

    float acc[2][8][4];
    #pragma unroll
    for (int a=0;a<2;a++)
      #pragma unroll
      for (int b=0;b<8;b++)
        #pragma unroll
        for (int c=0;c<4;c++) acc[a][b][c]=0.f;

    uint32_t b_hi = sb + (uint32_t)((m&1) ? B1HI : B0HI)*4 + b_toff;
    uint32_t b_lo = sb + (uint32_t)((m&1) ? B1LO : B0LO)*4 + b_toff;
    mma_core(a_hi, a_lo, b_hi, b_lo, acc);

    const float* bias = bs[m];
    float* Y = Ys[m];
    #pragma unroll
    for (int mt = 0; mt < 2; mt++){
      int r = row0 + mw*32 + mt*16 + tg;
      #pragma unroll
      for (int nt = 0; nt < 8; nt++){
        int col = nw*64 + nt*8 + tq*2;
        float2 bb = *(const float2*)(bias + col);
        if (r < NN)
          *(float2*)(Y + (size_t)r*CC + col) = make_float2(acc[mt][nt][0]+bb.x, acc[mt][nt][1]+bb.y);
        if (r + 8 < NN)
          *(float2*)(Y + (size_t)(r+8)*CC + col) = make_float2(acc[mt][nt][2]+bb.x, acc[mt][nt][3]+bb.y);
      }
    }
    __syncthreads();
  }
}

// ---------------- edge kernel ----------------
__global__ void k_edge(const int* __restrict__ src, const int* __restrict__ dst,
                       const float* __restrict__ Q, const float* __restrict__ K,
                       const float* __restrict__ V,
                       const float* __restrict__ t_src, const float* __restrict__ t_dst,
                       const int* __restrict__ ckeys, const int* __restrict__ cvals,
                       const int* __restrict__ rkeys,
                       const float* __restrict__ hb, const float* __restrict__ beta,
                       const float* __restrict__ tau_raw,
                       const float* __restrict__ gamma, const float* __restrict__ delta,
                       float* __restrict__ z, float* __restrict__ agg){
  int e = blockIdx.x*8 + (threadIdx.x>>5);
  int lane = threadIdx.x & 31;
  int s = src[e], d = dst[e];
  float4 q = __ldg((const float4*)(Q + (size_t)d*CC) + lane);
  float4 k = __ldg((const float4*)(K + (size_t)s*CC) + lane);
  float4 v = __ldg((const float4*)(V + (size_t)s*CC) + lane);
  float p = q.x*k.x + q.y*k.y + q.z*k.z + q.w*k.w;
  p += __shfl_xor_sync(0xffffffffu, p, 1);
  p += __shfl_xor_sync(0xffffffffu, p, 2);
  p += __shfl_xor_sync(0xffffffffu, p, 4);
  float tl=0.f, lc=0.f, rec=0.f;
  if (lane == 0){
    float traw = tau_raw[0];
    float tau = (traw > 20.f) ? traw : log1pf(expf(traw));
    tau += 1e-6f;
    float dt = fabsf(t_dst[d] - t_src[s]) + 1e-6f;
    tl = -log1pf(dt / tau);
    int pid = s*NN + d;
    int cnt = hcount(ckeys, cvals, pid) - 1;
    lc = log1pf((float)cnt);
    rec = hmember(rkeys, pid) ? 1.f : 0.f;
  }
  tl  = __shfl_sync(0xffffffffu, tl, 0);
  lc  = __shfl_sync(0xffffffffu, lc, 0);
  rec = __shfl_sync(0xffffffffu, rec, 0);
  int h = lane >> 3;
  float score = p * 0.17677669529663687f + hb[h] + tl*beta[h] + lc*gamma[h] + rec*delta[h];
  float w = expf(score);
  if ((lane & 7) == 0) atomicAdd(&z[(size_t)d*HH + h], w);
  float* ab = agg + (size_t)d*CC + lane*4;
  atomicAdd(ab+0, v.x*w);
  atomicAdd(ab+1, v.y*w);
  atomicAdd(ab+2, v.z*w);
  atomicAdd(ab+3, v.w*w);
}

// ---------------- epilogue: LN((agg/z)@Wo^T + indeg*bo + deg + x), both node types ----------------
__global__ __launch_bounds__(256,1) void k_out_mma(
    const float* __restrict__ aggu, const float* __restrict__ aggi,
    const float* __restrict__ zu, const float* __restrict__ zi,
    const float* __restrict__ bias,
    const int* __restrict__ indegu, const int* __restrict__ indegi,
    const int* __restrict__ degu, const int* __restrict__ degi,
    const float* __restrict__ xu, const float* __restrict__ xi,
    float* __restrict__ out){
  extern __shared__ uint32_t sm[];
  uint32_t sb = smem_u32(sm);
  int tid = threadIdx.x, lane = tid & 31, wid = tid >> 5;
  int mw = wid & 3, nw = wid >> 2, tg = lane >> 2, tq = lane & 3;
  int row0 = blockIdx.x * MT;
  const float* agg;  const float* z;  const int* indeg; const int* deg; const float* xres; float* o;
  if (blockIdx.y == 0){ agg=aggu; z=zu; indeg=indegu; deg=degu; xres=xu; o=out; }
  else { agg=aggi; z=zi; indeg=indegi; deg=degi; xres=xi; o=out + (size_t)NN*CC; }

  // prefetch B = Wo planes
  cpb(sb, B0HI, g_Whi[3]); cpb(sb, B0LO, g_Wlo[3]); CP_COMMIT();

  // stage A = agg/z (inline split)
  #pragma unroll
  for (int it = 0; it < 32; it++){
    int idx = tid + it*256;
    int row = idx >> 6, j = idx & 63;
    int gr = row0 + row;
    float2 v = make_float2(0.f, 0.f);
    if (gr < NN){
      float zz = z[(size_t)gr*HH + (j >> 4)];
      float inv = (zz > 0.f) ? (1.f/zz) : 0.f;
      float2 a = *(const float2*)(agg + (size_t)gr*CC + j*2);
      v = make_float2(a.x*inv, a.y*inv);
    }
    uint32_t hi, lo; bsplit(v.x, v.y, hi, lo);
    sm[AHI + row*PITCH + j] = hi;
    sm[ALO + row*PITCH + j] = lo;
  }
  CP_WAIT(0);
  __syncthreads();

  uint32_t a_toff = (uint32_t)(((mw*32 + (lane&15))*PITCH + (lane>>4)*4))*4;
  uint32_t b_toff = (uint32_t)(((nw*64 + (lane&7) + (lane>>4)*8)*PITCH + ((lane>>3)&1)*4))*4;

  float acc[2][8][4];
  #pragma unroll
  for (int a=0;a<2;a++)
    #pragma unroll
    for (int b=0;b<8;b++)
      #pragma unroll
      for (int c=0;c<4;c++) acc[a][b][c]=0.f;

  mma_core(sb + (uint32_t)AHI*4 + a_toff, sb + (uint32_t)ALO*4 + a_toff,
           sb + (uint32_t)B0HI*4 + b_toff, sb + (uint32_t)B0LO*4 + b_toff, acc);

  float* reds = (float*)(sm + RED0);
  float* redq = (float*)(sm + RED0 + 256);

  float2 bb[8];
  #pragma unroll
  for (int nt = 0; nt < 8; nt++) bb[nt] = *(const float2*)(bias + nw*64 + nt*8 + tq*2);

  #pragma unroll
  for (int mt = 0; mt < 2; mt++){
    #pragma unroll
    for (int h = 0; h < 2; h++){
      int lr = mw*32 + mt*16 + tg + h*8;
      int grow = row0 + lr;
      float dg = 0.f, idg = 0.f;
      if (grow < NN){ dg = (float)deg[grow]; idg = (float)indeg[grow]; }
      float s = 0.f;
      #pragma unroll
      for (int nt = 0; nt < 8; nt++){
        int col = nw*64 + nt*8 + tq*2;
        float2 xr = make_float2(0.f, 0.f);
        if (grow < NN) xr = *(const float2*)(xres + (size_t)grow*CC + col);
        float v0 = acc[mt][nt][h*2+0] + bb[nt].x*idg + dg + xr.x;
        float v1 = acc[mt][nt][h*2+1] + bb[nt].y*idg + dg + xr.y;
        acc[mt][nt][h*2+0] = v0;
        acc[mt][nt][h*2+1] = v1;
        s += v0 + v1;
      }
      s += __shfl_xor_sync(0xffffffffu, s, 1);
      s += __shfl_xor_sync(0xffffffffu, s, 2);
      if (tq == 0) reds[lr*2 + nw] = s;
    }
  }
  __syncthreads();

  float mu[2][2];
  #pragma unroll
  for (int mt = 0; mt < 2; mt++)
    #pragma unroll
    for (int h = 0; h < 2; h++){
      int lr = mw*32 + mt*16 + tg + h*8;
      mu[mt][h] = (reds[lr*2] + reds[lr*2+1]) * (1.f/128.f);
    }

  #pragma unroll
  for (int mt = 0; mt < 2; mt++){
    #pragma unroll
    for (int h = 0; h < 2; h++){
      int lr = mw*32 + mt*16 + tg + h*8;
      float q = 0.f;
      #pragma unroll
      for (int nt = 0; nt < 8; nt++){
        float d0 = acc[mt][nt][h*2+0] - mu[mt][h];
        float d1 = acc[mt][nt][h*2+1] - mu[mt][h];
        q += d0*d0 + d1*d1;
      }
      q += __shfl_xor_sync(0xffffffffu, q, 1);
      q += __shfl_xor_sync(0xffffffffu, q, 2);
      if (tq == 0) redq[lr*2 + nw] = q;
    }
  }
  __syncthreads();

  #pragma unroll
  for (int mt = 0; mt < 2; mt++){
    #pragma unroll
    for (int h = 0; h < 2; h++){
      int lr = mw*32 + mt*16 + tg + h*8;
      int grow = row0 + lr;
      if (grow >= NN) continue;
      float var = (redq[lr*2] + redq[lr*2+1]) * (1.f/128.f);
      float rs = rsqrtf(var + 1e-5f);
      float m = mu[mt][h];
      #pragma unroll
      for (int nt = 0; nt < 8; nt++){
        int col = nw*64 + nt*8 + tq*2;
        *(float2*)(o + (size_t)grow*CC + col) =
          make_float2((acc[mt][nt][h*2+0]-m)*rs, (acc[mt][nt][h*2+1]-m)*rs);
      }
    }
  }
}

// ---------------- launch ----------------
extern "C" void kernel_launch(void* const* d_in, const int* in_sizes, int n_in,
                              void* d_out, int out_size){
  const float* x_user=(const float*)d_in[0];
  const float* x_item=(const float*)d_in[1];
  const float* t_user=(const float*)d_in[2];
  const float* t_item=(const float*)d_in[3];
  const int*   eui  =(const int*)  d_in[4];
  const int*   eiu  =(const int*)  d_in[5];
  const float* Wq=(const float*)d_in[6];  const float* bq=(const float*)d_in[7];
  const float* Wk=(const float*)d_in[8];  const float* bk=(const float*)d_in[9];
  const float* Wv=(const float*)d_in[10]; const float* bv=(const float*)d_in[11];
  const float* Wo=(const float*)d_in[12]; const float* bo=(const float*)d_in[13];
  const float* hb=(const float*)d_in[14];
  const float* tb=(const float*)d_in[15];
  const float* traw=(const float*)d_in[16];
  const float* gm=(const float*)d_in[17];
  const float* dr=(const float*)d_in[18];
  float* out=(float*)d_out;

  float *Qu,*Ku,*Vu,*Qi,*Ki,*Vi,*aggu,*aggi,*zu,*zi;
  int *cku,*cvu,*cki,*cvi,*rku,*rki,*degu,*degi,*idgu,*idgi;
  cudaGetSymbolAddress((void**)&Qu, g_Qu);
  cudaGetSymbolAddress((void**)&Ku, g_Ku);
  cudaGetSymbolAddress((void**)&Vu, g_Vu);
  cudaGetSymbolAddress((void**)&Qi, g_Qi);
  cudaGetSymbolAddress((void**)&Ki, g_Ki);
  cudaGetSymbolAddress((void**)&Vi, g_Vi);
  cudaGetSymbolAddress((void**)&aggu, g_agg_u);
  cudaGetSymbolAddress((void**)&aggi, g_agg_i);
  cudaGetSymbolAddress((void**)&zu, g_z_u);
  cudaGetSymbolAddress((void**)&zi, g_z_i);
  cudaGetSymbolAddress((void**)&cku, g_ck_ui);
  cudaGetSymbolAddress((void**)&cvu, g_cv_ui);
  cudaGetSymbolAddress((void**)&cki, g_ck_iu);
  cudaGetSymbolAddress((void**)&cvi, g_cv_iu);
  cudaGetSymbolAddress((void**)&rku, g_rk_ui);
  cudaGetSymbolAddress((void**)&rki, g_rk_iu);
  cudaGetSymbolAddress((void**)&degu, g_deg_u);
  cudaGetSymbolAddress((void**)&degi, g_deg_i);
  cudaGetSymbolAddress((void**)&idgu, g_indeg_u);
  cudaGetSymbolAddress((void**)&idgi, g_indeg_i);

  cudaFuncSetAttribute(k_qkv3,   cudaFuncAttributeMaxDynamicSharedMemorySize, QKV_SMEMB);
  cudaFuncSetAttribute(k_out_mma,cudaFuncAttributeMaxDynamicSharedMemorySize, OUT_SMEMB);

  k_init<<<2048,256>>>();
  k_build<<<(2*EE+255)/256,256>>>(eui, eiu);
  k_wsplit<<<dim3(32,4),256>>>(Wq, Wk, Wv, Wo);

  // fused QKV projections, both node types in one launch
  k_qkv3<<<dim3(NBLK,2),256,QKV_SMEMB>>>(x_user, x_item, Qu,Ku,Vu, Qi,Ki,Vi, bq,bk,bv);

  // relation user->item (rel 0): Q from items (dst), K/V from users (src)
  k_edge<<<EE/8,256>>>(eui, eui+EE, Qi, Ku, Vu, t_user, t_item,
                       cku, cvu, rku, hb, tb, traw, gm, dr, zi, aggi);
  // relation item->user (rel 1)
  k_edge<<<EE/8,256>>>(eiu, eiu+EE, Qu, Ki, Vi, t_item, t_user,
                       cki, cvi, rki, hb+HH, tb+HH, traw+1, gm+HH, dr+HH, zu, aggu);

  // fused Wo + indeg*bo + deg + residual + layernorm, both node types
  k_out_mma<<<dim3(NBLK,2),256,OUT_SMEMB>>>(aggu, aggi, zu, zi, bo,
                                            idgu, idgi, degu, degi,
                                            x_user, x_item, out);
}

// round 5
// speedup vs baseline: 1.5479x; 1.5479x over previous
#include <cuda_runtime.h>
#include <cuda_bf16.h>
#include <math.h>
#include <stdint.h>

#define NN 40000
#define CC 128
#define HH 4
#define EE 200000
#define TS (1u<<19)
#define TMASK (TS-1u)

#define MT 128
#define NBLK ((NN + MT - 1) / MT)        // 313
#define PITCH 68
#define PLANE (128*PITCH)                // 8704 words
#define AHI 0
#define ALO PLANE
#define B0HI (2*PLANE)
#define B0LO (3*PLANE)
#define B1HI (4*PLANE)
#define B1LO (5*PLANE)
#define RED0 (4*PLANE)                   // k_out only (reuses B1 space)
#define QKV_SMEMB (6*PLANE*4)            // 208896 B
#define OUT_SMEMB ((4*PLANE+512)*4)      // 141312 B

// ---------------- scratch (device globals) ----------------
__device__ float g_Qu[NN*CC], g_Ku[NN*CC], g_Vu[NN*CC];
__device__ float g_Qi[NN*CC], g_Ki[NN*CC], g_Vi[NN*CC];
__device__ float g_agg_u[NN*CC], g_agg_i[NN*CC];
__device__ uint32_t g_Whi[4][CC*CC/2], g_Wlo[4][CC*CC/2];   // q,k,v,o
__device__ int g_ck_ui[TS], g_cv_ui[TS];
__device__ int g_ck_iu[TS], g_cv_iu[TS];
__device__ int g_rk_ui[TS], g_rk_iu[TS];
__device__ int g_deg_u[NN], g_deg_i[NN], g_indeg_u[NN], g_indeg_i[NN];
__device__ int g_off_i[NN+1], g_off_u[NN+1];
__device__ int g_cur_i[NN], g_cur_u[NN];
__device__ int g_csr_ui[EE], g_csr_iu[EE];   // src ids grouped by dst

// ---------------- helpers ----------------
__device__ __forceinline__ uint32_t smem_u32(const void* p){
  uint32_t a;
  asm("{ .reg .u64 t; cvta.to.shared.u64 t, %1; cvt.u32.u64 %0, t; }" : "=r"(a) : "l"(p));
  return a;
}
__device__ __forceinline__ void bsplit(float a, float b, uint32_t& hi, uint32_t& lo){
  __nv_bfloat16 ha = __float2bfloat16(a), hb = __float2bfloat16(b);
  float ra = a - __bfloat162float(ha);
  float rb = b - __bfloat162float(hb);
  __nv_bfloat16 la = __float2bfloat16(ra), lb = __float2bfloat16(rb);
  hi = ((uint32_t)__bfloat16_as_ushort(hb) << 16) | (uint32_t)__bfloat16_as_ushort(ha);
  lo = ((uint32_t)__bfloat16_as_ushort(lb) << 16) | (uint32_t)__bfloat16_as_ushort(la);
}
__device__ __forceinline__ void mma_bf16(float* c,
    uint32_t a0, uint32_t a1, uint32_t a2, uint32_t a3,
    uint32_t b0, uint32_t b1){
  asm volatile("mma.sync.aligned.m16n8k16.row.col.f32.bf16.bf16.f32 "
    "{%0,%1,%2,%3}, {%4,%5,%6,%7}, {%8,%9}, {%0,%1,%2,%3};"
    : "+f"(c[0]), "+f"(c[1]), "+f"(c[2]), "+f"(c[3])
    : "r"(a0), "r"(a1), "r"(a2), "r"(a3), "r"(b0), "r"(b1));
}
__device__ __forceinline__ void ldsm4(uint32_t* r, uint32_t addr){
  asm volatile("ldmatrix.sync.aligned.m8n8.x4.shared.b16 {%0,%1,%2,%3}, [%4];"
    : "=r"(r[0]), "=r"(r[1]), "=r"(r[2]), "=r"(r[3]) : "r"(addr));
}
#define CP_ASYNC16(dst, src) asm volatile("cp.async.cg.shared.global [%0], [%1], 16;" :: "r"(dst), "l"(src))
#define CP_COMMIT()  asm volatile("cp.async.commit_group;" ::: "memory")
#define CP_WAIT(n)   asm volatile("cp.async.wait_group %0;" :: "n"(n) : "memory")

__device__ __forceinline__ void cpb(uint32_t sb, int wbase, const uint32_t* __restrict__ gsrc){
  int tid = threadIdx.x;
  #pragma unroll
  for (int it = 0; it < 8; it++){
    int c = tid + it*256;
    int row = c >> 4, cw = (c & 15) * 4;
    CP_ASYNC16(sb + (uint32_t)(wbase + row*PITCH + cw)*4, gsrc + row*64 + cw);
  }
}

__device__ __forceinline__ void mma_core(uint32_t a_hi, uint32_t a_lo,
                                         uint32_t b_hi, uint32_t b_lo,
                                         float acc[2][8][4]){
  #pragma unroll
  for (int s = 0; s < 8; s++){
    uint32_t k2b = s*32;
    uint32_t ah[2][4], al[2][4];
    ldsm4(ah[0], a_hi + k2b);
    ldsm4(ah[1], a_hi + 16*PITCH*4 + k2b);
    ldsm4(al[0], a_lo + k2b);
    ldsm4(al[1], a_lo + 16*PITCH*4 + k2b);
    uint32_t bh[4][4], bl[4][4];
    #pragma unroll
    for (int p = 0; p < 4; p++){
      ldsm4(bh[p], b_hi + (uint32_t)p*16*PITCH*4 + k2b);
      ldsm4(bl[p], b_lo + (uint32_t)p*16*PITCH*4 + k2b);
    }
    #pragma unroll
    for (int p = 0; p < 4; p++)
      #pragma unroll
      for (int e = 0; e < 2; e++){
        int nt = p*2 + e;
        uint32_t b0h = bh[p][e*2], b1h = bh[p][e*2+1];
        uint32_t b0l = bl[p][e*2], b1l = bl[p][e*2+1];
        #pragma unroll
        for (int mt = 0; mt < 2; mt++){
          mma_bf16(acc[mt][nt], ah[mt][0],ah[mt][1],ah[mt][2],ah[mt][3], b0h, b1h);
          mma_bf16(acc[mt][nt], ah[mt][0],ah[mt][1],ah[mt][2],ah[mt][3], b0l, b1l);
          mma_bf16(acc[mt][nt], al[mt][0],al[mt][1],al[mt][2],al[mt][3], b0h, b1h);
        }
      }
  }
}

// ---------------- hash helpers ----------------
__device__ __forceinline__ unsigned hmix(int k){
  unsigned x = (unsigned)k; x *= 2654435761u; x ^= x >> 15; return x & TMASK;
}
__device__ __forceinline__ void hinsert_count(int* keys, int* vals, int key){
  unsigned slot = hmix(key);
  while (true){
    int prev = atomicCAS(&keys[slot], -1, key);
    if (prev == -1 || prev == key){ atomicAdd(&vals[slot], 1); return; }
    slot = (slot + 1) & TMASK;
  }
}
__device__ __forceinline__ void hinsert_set(int* keys, int key){
  unsigned slot = hmix(key);
  while (true){
    int prev = atomicCAS(&keys[slot], -1, key);
    if (prev == -1 || prev == key) return;
    slot = (slot + 1) & TMASK;
  }
}
__device__ __forceinline__ int hcount(const int* __restrict__ keys, const int* __restrict__ vals, int key){
  unsigned slot = hmix(key);
  while (true){
    int k = keys[slot];
    if (k == key) return vals[slot];
    if (k == -1) return 0;
    slot = (slot + 1) & TMASK;
  }
}
__device__ __forceinline__ bool hmember(const int* __restrict__ keys, int key){
  unsigned slot = hmix(key);
  while (true){
    int k = keys[slot];
    if (k == key) return true;
    if (k == -1) return false;
    slot = (slot + 1) & TMASK;
  }
}

// ---------------- init / build / wsplit / scan / scatter ----------------
__global__ void k_init(){
  int i = blockIdx.x*blockDim.x + threadIdx.x;
  int stride = gridDim.x*blockDim.x;
  for (int j=i;j<(int)TS;j+=stride){
    g_ck_ui[j]=-1; g_ck_iu[j]=-1; g_rk_ui[j]=-1; g_rk_iu[j]=-1;
    g_cv_ui[j]=0;  g_cv_iu[j]=0;
  }
  for (int j=i;j<NN;j+=stride){ g_deg_u[j]=0; g_deg_i[j]=0; g_indeg_u[j]=0; g_indeg_i[j]=0; }
}

__global__ void k_build(const int* __restrict__ eui, const int* __restrict__ eiu){
  int i = blockIdx.x*blockDim.x + threadIdx.x;
  if (i < EE){
    int su = eui[i], du = eui[EE+i];
    hinsert_count(g_ck_ui, g_cv_ui, su*NN + du);
    hinsert_set  (g_rk_iu, du*NN + su);
    atomicAdd(&g_deg_u[su],1); atomicAdd(&g_deg_i[du],1); atomicAdd(&g_indeg_i[du],1);
  } else if (i < 2*EE){
    int j = i - EE;
    int si = eiu[j], di = eiu[EE+j];
    hinsert_count(g_ck_iu, g_cv_iu, si*NN + di);
    hinsert_set  (g_rk_ui, di*NN + si);
    atomicAdd(&g_deg_i[si],1); atomicAdd(&g_deg_u[di],1); atomicAdd(&g_indeg_u[di],1);
  }
}

__global__ void k_wsplit(const float* __restrict__ Wq, const float* __restrict__ Wk,
                         const float* __restrict__ Wv, const float* __restrict__ Wo){
  const float* Ws[4] = {Wq, Wk, Wv, Wo};
  int m = blockIdx.y;
  int i = blockIdx.x*256 + threadIdx.x;
  float2 v = *(const float2*)(Ws[m] + i*2);
  uint32_t hi, lo; bsplit(v.x, v.y, hi, lo);
  g_Whi[m][i] = hi; g_Wlo[m][i] = lo;
}

// exclusive prefix sum of indeg (NN values) -> off, cur.  1 CTA, 1024 threads.
__global__ void k_scan(const int* __restrict__ indeg, int* __restrict__ off, int* __restrict__ cur){
  __shared__ int part[1025];
  int tid = threadIdx.x;
  const int per = 40;                    // 1024*40 >= NN
  int base = tid*per;
  int s = 0;
  for (int j=0;j<per;j++){ int idx=base+j; if (idx<NN) s += indeg[idx]; }
  part[tid] = s;
  __syncthreads();
  if (tid == 0){
    int run = 0;
    for (int i=0;i<1024;i++){ int t=part[i]; part[i]=run; run+=t; }
    part[1024]=run;
  }
  __syncthreads();
  int run = part[tid];
  for (int j=0;j<per;j++){
    int idx = base+j;
    if (idx<NN){ off[idx]=run; cur[idx]=run; run += indeg[idx]; }
  }
  if (tid==1023) off[NN]=part[1024];
}

__global__ void k_scatter(const int* __restrict__ eui, const int* __restrict__ eiu){
  int i = blockIdx.x*blockDim.x + threadIdx.x;
  if (i < EE){
    int s = eui[i], d = eui[EE+i];
    int pos = atomicAdd(&g_cur_i[d], 1);
    g_csr_ui[pos] = s;
  } else if (i < 2*EE){
    int j = i - EE;
    int s = eiu[j], d = eiu[EE+j];
    int pos = atomicAdd(&g_cur_u[d], 1);
    g_csr_iu[pos] = s;
  }
}

// ---------------- fused QKV GEMMs ----------------
__global__ __launch_bounds__(256,1) void k_qkv3(
    const float* __restrict__ Xu, const float* __restrict__ Xi,
    float* __restrict__ Qu, float* __restrict__ Ku, float* __restrict__ Vu,
    float* __restrict__ Qi, float* __restrict__ Ki, float* __restrict__ Vi,
    const float* __restrict__ bq, const float* __restrict__ bk, const float* __restrict__ bv){
  extern __shared__ uint32_t sm[];
  uint32_t sb = smem_u32(sm);
  int tid = threadIdx.x, lane = tid & 31, wid = tid >> 5;
  int mw = wid & 3, nw = wid >> 2, tg = lane >> 2, tq = lane & 3;
  int row0 = blockIdx.x * MT;
  const float* X = blockIdx.y ? Xi : Xu;
  float* Ys[3];
  if (blockIdx.y == 0){ Ys[0]=Qu; Ys[1]=Ku; Ys[2]=Vu; }
  else               { Ys[0]=Qi; Ys[1]=Ki; Ys[2]=Vi; }
  const float* bs[3] = {bq, bk, bv};

  #pragma unroll
  for (int it = 0; it < 32; it++){
    int idx = tid + it*256;
    int row = idx >> 6, j = idx & 63;
    int gr = row0 + row;
    float2 v = make_float2(0.f, 0.f);
    if (gr < NN) v = *(const float2*)(X + (size_t)gr*CC + j*2);
    uint32_t hi, lo; bsplit(v.x, v.y, hi, lo);
    sm[AHI + row*PITCH + j] = hi;
    sm[ALO + row*PITCH + j] = lo;
  }

  cpb(sb, B0HI, g_Whi[0]); cpb(sb, B0LO, g_Wlo[0]); CP_COMMIT();

  uint32_t a_toff = (uint32_t)(((mw*32 + (lane&15))*PITCH + (lane>>4)*4))*4;
  uint32_t b_toff = (uint32_t)(((nw*64 + (lane&7) + (lane>>4)*8)*PITCH + ((lane>>3)&1)*4))*4;
  uint32_t a_hi = sb + (uint32_t)AHI*4 + a_toff;
  uint32_t a_lo = sb + (uint32_t)ALO*4 + a_toff;

  #pragma unroll
  for (int m = 0; m < 3; m++){
    if (m < 2){
      int wb_hi = ((m+1)&1) ? B1HI : B0HI;
      int wb_lo = ((m+1)&1) ? B1LO : B0LO;
      cpb(sb, wb_hi, g_Whi[m+1]); cpb(sb, wb_lo, g_Wlo[m+1]); CP_COMMIT();
      CP_WAIT(1);
    } else {
      CP_WAIT(0);
    }
    __syncthreads();

    float acc[2][8][4];
    #pragma unroll
    for (int a=0;a<2;a++)
      #pragma unroll
      for (int b=0;b<8;b++)
        #pragma unroll
        for (int c=0;c<4;c++) acc[a][b][c]=0.f;

    uint32_t b_hi = sb + (uint32_t)((m&1) ? B1HI : B0HI)*4 + b_toff;
    uint32_t b_lo = sb + (uint32_t)((m&1) ? B1LO : B0LO)*4 + b_toff;
    mma_core(a_hi, a_lo, b_hi, b_lo, acc);

    const float* bias = bs[m];
    float* Y = Ys[m];
    #pragma unroll
    for (int mt = 0; mt < 2; mt++){
      int r = row0 + mw*32 + mt*16 + tg;
      #pragma unroll
      for (int nt = 0; nt < 8; nt++){
        int col = nw*64 + nt*8 + tq*2;
        float2 bb = *(const float2*)(bias + col);
        if (r < NN)
          *(float2*)(Y + (size_t)r*CC + col) = make_float2(acc[mt][nt][0]+bb.x, acc[mt][nt][1]+bb.y);
        if (r + 8 < NN)
          *(float2*)(Y + (size_t)(r+8)*CC + col) = make_float2(acc[mt][nt][2]+bb.x, acc[mt][nt][3]+bb.y);
      }
    }
    __syncthreads();
  }
}

// ---------------- CSR aggregation: warp per destination, no atomics ----------------
__global__ __launch_bounds__(256) void k_agg(
    const int* __restrict__ off, const int* __restrict__ csrc,
    const float* __restrict__ Q, const float* __restrict__ K, const float* __restrict__ V,
    const float* __restrict__ t_src, const float* __restrict__ t_dst,
    const int* __restrict__ ckeys, const int* __restrict__ cvals, const int* __restrict__ rkeys,
    const float* __restrict__ hb, const float* __restrict__ beta,
    const float* __restrict__ tau_raw,
    const float* __restrict__ gamma, const float* __restrict__ delta,
    float* __restrict__ agg){
  int d = blockIdx.x*8 + (threadIdx.x>>5);
  if (d >= NN) return;
  int lane = threadIdx.x & 31;
  int h = lane >> 3;
  int beg = off[d], end = off[d+1];
  float4 q = __ldg((const float4*)(Q + (size_t)d*CC) + lane);
  float hbh = hb[h], bh = beta[h], gh = gamma[h], dh = delta[h];
  float traw = tau_raw[0];
  float tau = (traw > 20.f) ? traw : log1pf(expf(traw));
  tau += 1e-6f;
  float td = t_dst[d];
  float4 acc = make_float4(0.f,0.f,0.f,0.f);
  float z = 0.f;
  for (int base = beg; base < end; base += 32){
    int m = end - base; if (m > 32) m = 32;
    int s = 0; float tl = 0.f, lc = 0.f, rec = 0.f;
    if (lane < m){
      s = csrc[base + lane];
      float dt = fabsf(td - t_src[s]) + 1e-6f;
      tl = -log1pf(dt / tau);
      int pid = s*NN + d;
      lc = log1pf((float)(hcount(ckeys, cvals, pid) - 1));
      rec = hmember(rkeys, pid) ? 1.f : 0.f;
    }
    for (int j = 0; j < m; j++){
      int sj    = __shfl_sync(0xffffffffu, s,   j);
      float tlj = __shfl_sync(0xffffffffu, tl,  j);
      float lcj = __shfl_sync(0xffffffffu, lc,  j);
      float rcj = __shfl_sync(0xffffffffu, rec, j);
      float4 kk = __ldg((const float4*)(K + (size_t)sj*CC) + lane);
      float4 vv = __ldg((const float4*)(V + (size_t)sj*CC) + lane);
      float p = q.x*kk.x + q.y*kk.y + q.z*kk.z + q.w*kk.w;
      p += __shfl_xor_sync(0xffffffffu, p, 1);
      p += __shfl_xor_sync(0xffffffffu, p, 2);
      p += __shfl_xor_sync(0xffffffffu, p, 4);
      float sc = p*0.17677669529663687f + hbh + tlj*bh + lcj*gh + rcj*dh;
      float w = expf(sc);
      z += w;
      acc.x += vv.x*w; acc.y += vv.y*w; acc.z += vv.z*w; acc.w += vv.w*w;
    }
  }
  float inv = (z > 0.f) ? (1.f/z) : 0.f;
  *(float4*)(agg + (size_t)d*CC + lane*4) =
      make_float4(acc.x*inv, acc.y*inv, acc.z*inv, acc.w*inv);
}

// ---------------- epilogue: LN(agg@Wo^T + indeg*bo + deg + x), both node types ----------------
__global__ __launch_bounds__(256,1) void k_out_mma(
    const float* __restrict__ aggu, const float* __restrict__ aggi,
    const float* __restrict__ bias,
    const int* __restrict__ indegu, const int* __restrict__ indegi,
    const int* __restrict__ degu, const int* __restrict__ degi,
    const float* __restrict__ xu, const float* __restrict__ xi,
    float* __restrict__ out){
  extern __shared__ uint32_t sm[];
  uint32_t sb = smem_u32(sm);
  int tid = threadIdx.x, lane = tid & 31, wid = tid >> 5;
  int mw = wid & 3, nw = wid >> 2, tg = lane >> 2, tq = lane & 3;
  int row0 = blockIdx.x * MT;
  const float* agg; const int* indeg; const int* deg; const float* xres; float* o;
  if (blockIdx.y == 0){ agg=aggu; indeg=indegu; deg=degu; xres=xu; o=out; }
  else { agg=aggi; indeg=indegi; deg=degi; xres=xi; o=out + (size_t)NN*CC; }

  cpb(sb, B0HI, g_Whi[3]); cpb(sb, B0LO, g_Wlo[3]); CP_COMMIT();

  #pragma unroll
  for (int it = 0; it < 32; it++){
    int idx = tid + it*256;
    int row = idx >> 6, j = idx & 63;
    int gr = row0 + row;
    float2 v = make_float2(0.f, 0.f);
    if (gr < NN) v = *(const float2*)(agg + (size_t)gr*CC + j*2);
    uint32_t hi, lo; bsplit(v.x, v.y, hi, lo);
    sm[AHI + row*PITCH + j] = hi;
    sm[ALO + row*PITCH + j] = lo;
  }
  CP_WAIT(0);
  __syncthreads();

  uint32_t a_toff = (uint32_t)(((mw*32 + (lane&15))*PITCH + (lane>>4)*4))*4;
  uint32_t b_toff = (uint32_t)(((nw*64 + (lane&7) + (lane>>4)*8)*PITCH + ((lane>>3)&1)*4))*4;

  float acc[2][8][4];
  #pragma unroll
  for (int a=0;a<2;a++)
    #pragma unroll
    for (int b=0;b<8;b++)
      #pragma unroll
      for (int c=0;c<4;c++) acc[a][b][c]=0.f;

  mma_core(sb + (uint32_t)AHI*4 + a_toff, sb + (uint32_t)ALO*4 + a_toff,
           sb + (uint32_t)B0HI*4 + b_toff, sb + (uint32_t)B0LO*4 + b_toff, acc);

  float* reds = (float*)(sm + RED0);
  float* redq = (float*)(sm + RED0 + 256);

  float2 bb[8];
  #pragma unroll
  for (int nt = 0; nt < 8; nt++) bb[nt] = *(const float2*)(bias + nw*64 + nt*8 + tq*2);

  #pragma unroll
  for (int mt = 0; mt < 2; mt++){
    #pragma unroll
    for (int h = 0; h < 2; h++){
      int lr = mw*32 + mt*16 + tg + h*8;
      int grow = row0 + lr;
      float dg = 0.f, idg = 0.f;
      if (grow < NN){ dg = (float)deg[grow]; idg = (float)indeg[grow]; }
      float s = 0.f;
      #pragma unroll
      for (int nt = 0; nt < 8; nt++){
        int col = nw*64 + nt*8 + tq*2;
        float2 xr = make_float2(0.f, 0.f);
        if (grow < NN) xr = *(const float2*)(xres + (size_t)grow*CC + col);
        float v0 = acc[mt][nt][h*2+0] + bb[nt].x*idg + dg + xr.x;
        float v1 = acc[mt][nt][h*2+1] + bb[nt].y*idg + dg + xr.y;
        acc[mt][nt][h*2+0] = v0;
        acc[mt][nt][h*2+1] = v1;
        s += v0 + v1;
      }
      s += __shfl_xor_sync(0xffffffffu, s, 1);
      s += __shfl_xor_sync(0xffffffffu, s, 2);
      if (tq == 0) reds[lr*2 + nw] = s;
    }
  }
  __syncthreads();

  float mu[2][2];
  #pragma unroll
  for (int mt = 0; mt < 2; mt++)
    #pragma unroll
    for (int h = 0; h < 2; h++){
      int lr = mw*32 + mt*16 + tg + h*8;
      mu[mt][h] = (reds[lr*2] + reds[lr*2+1]) * (1.f/128.f);
    }

  #pragma unroll
  for (int mt = 0; mt < 2; mt++){
    #pragma unroll
    for (int h = 0; h < 2; h++){
      int lr = mw*32 + mt*16 + tg + h*8;
      float q = 0.f;
      #pragma unroll
      for (int nt = 0; nt < 8; nt++){
        float d0 = acc[mt][nt][h*2+0] - mu[mt][h];
        float d1 = acc[mt][nt][h*2+1] - mu[mt][h];
        q += d0*d0 + d1*d1;
      }
      q += __shfl_xor_sync(0xffffffffu, q, 1);
      q += __shfl_xor_sync(0xffffffffu, q, 2);
      if (tq == 0) redq[lr*2 + nw] = q;
    }
  }
  __syncthreads();

  #pragma unroll
  for (int mt = 0; mt < 2; mt++){
    #pragma unroll
    for (int h = 0; h < 2; h++){
      int lr = mw*32 + mt*16 + tg + h*8;
      int grow = row0 + lr;
      if (grow >= NN) continue;
      float var = (redq[lr*2] + redq[lr*2+1]) * (1.f/128.f);
      float rs = rsqrtf(var + 1e-5f);
      float m = mu[mt][h];
      #pragma unroll
      for (int nt = 0; nt < 8; nt++){
        int col = nw*64 + nt*8 + tq*2;
        *(float2*)(o + (size_t)grow*CC + col) =
          make_float2((acc[mt][nt][h*2+0]-m)*rs, (acc[mt][nt][h*2+1]-m)*rs);
      }
    }
  }
}

// ---------------- launch ----------------
extern "C" void kernel_launch(void* const* d_in, const int* in_sizes, int n_in,
                              void* d_out, int out_size){
  const float* x_user=(const float*)d_in[0];
  const float* x_item=(const float*)d_in[1];
  const float* t_user=(const float*)d_in[2];
  const float* t_item=(const float*)d_in[3];
  const int*   eui  =(const int*)  d_in[4];
  const int*   eiu  =(const int*)  d_in[5];
  const float* Wq=(const float*)d_in[6];  const float* bq=(const float*)d_in[7];
  const float* Wk=(const float*)d_in[8];  const float* bk=(const float*)d_in[9];
  const float* Wv=(const float*)d_in[10]; const float* bv=(const float*)d_in[11];
  const float* Wo=(const float*)d_in[12]; const float* bo=(const float*)d_in[13];
  const float* hb=(const float*)d_in[14];
  const float* tb=(const float*)d_in[15];
  const float* traw=(const float*)d_in[16];
  const float* gm=(const float*)d_in[17];
  const float* dr=(const float*)d_in[18];
  float* out=(float*)d_out;

  float *Qu,*Ku,*Vu,*Qi,*Ki,*Vi,*aggu,*aggi;
  int *cku,*cvu,*cki,*cvi,*rku,*rki,*degu,*degi,*idgu,*idgi;
  int *offi,*offu,*curi,*curu,*csrui,*csriu;
  cudaGetSymbolAddress((void**)&Qu, g_Qu);
  cudaGetSymbolAddress((void**)&Ku, g_Ku);
  cudaGetSymbolAddress((void**)&Vu, g_Vu);
  cudaGetSymbolAddress((void**)&Qi, g_Qi);
  cudaGetSymbolAddress((void**)&Ki, g_Ki);
  cudaGetSymbolAddress((void**)&Vi, g_Vi);
  cudaGetSymbolAddress((void**)&aggu, g_agg_u);
  cudaGetSymbolAddress((void**)&aggi, g_agg_i);
  cudaGetSymbolAddress((void**)&cku, g_ck_ui);
  cudaGetSymbolAddress((void**)&cvu, g_cv_ui);
  cudaGetSymbolAddress((void**)&cki, g_ck_iu);
  cudaGetSymbolAddress((void**)&cvi, g_cv_iu);
  cudaGetSymbolAddress((void**)&rku, g_rk_ui);
  cudaGetSymbolAddress((void**)&rki, g_rk_iu);
  cudaGetSymbolAddress((void**)&degu, g_deg_u);
  cudaGetSymbolAddress((void**)&degi, g_deg_i);
  cudaGetSymbolAddress((void**)&idgu, g_indeg_u);
  cudaGetSymbolAddress((void**)&idgi, g_indeg_i);
  cudaGetSymbolAddress((void**)&offi, g_off_i);
  cudaGetSymbolAddress((void**)&offu, g_off_u);
  cudaGetSymbolAddress((void**)&curi, g_cur_i);
  cudaGetSymbolAddress((void**)&curu, g_cur_u);
  cudaGetSymbolAddress((void**)&csrui, g_csr_ui);
  cudaGetSymbolAddress((void**)&csriu, g_csr_iu);

  cudaFuncSetAttribute(k_qkv3,   cudaFuncAttributeMaxDynamicSharedMemorySize, QKV_SMEMB);
  cudaFuncSetAttribute(k_out_mma,cudaFuncAttributeMaxDynamicSharedMemorySize, OUT_SMEMB);

  k_init<<<1024,256>>>();
  k_build<<<(2*EE+255)/256,256>>>(eui, eiu);
  k_wsplit<<<dim3(32,4),256>>>(Wq, Wk, Wv, Wo);
  k_scan<<<1,1024>>>(idgi, offi, curi);
  k_scan<<<1,1024>>>(idgu, offu, curu);
  k_scatter<<<(2*EE+255)/256,256>>>(eui, eiu);

  k_qkv3<<<dim3(NBLK,2),256,QKV_SMEMB>>>(x_user, x_item, Qu,Ku,Vu, Qi,Ki,Vi, bq,bk,bv);

  // relation user->item (rel 0): dst=items; Q=Qi, K/V from users
  k_agg<<<(NN+7)/8,256>>>(offi, csrui, Qi, Ku, Vu, t_user, t_item,
                          cku, cvu, rku, hb, tb, traw, gm, dr, aggi);
  // relation item->user (rel 1): dst=users; Q=Qu, K/V from items
  k_agg<<<(NN+7)/8,256>>>(offu, csriu, Qu, Ki, Vi, t_item, t_user,
                          cki, cvi, rki, hb+HH, tb+HH, traw+1, gm+HH, dr+HH, aggu);

  k_out_mma<<<dim3(NBLK,2),256,OUT_SMEMB>>>(aggu, aggi, bo,
                                            idgu, idgi, degu, degi,
                                            x_user, x_item, out);
}

// round 7
// speedup vs baseline: 1.7031x; 1.1003x over previous
#include <cuda_runtime.h>
#include <cuda_bf16.h>
#include <math.h>
#include <stdint.h>

#define NN 40000
#define CC 128
#define HH 4
#define EE 200000
#define TS (1u<<19)
#define TMASK (TS-1u)

#define MT 128
#define NBLK ((NN + MT - 1) / MT)        // 313
#define PITCH 68
#define PLANE (128*PITCH)                // 8704 words
#define AHI 0
#define ALO PLANE
#define B0HI (2*PLANE)
#define B0LO (3*PLANE)
#define B1HI (4*PLANE)
#define B1LO (5*PLANE)
#define RED0 (4*PLANE)                   // k_out only (reuses B1 space)
#define QKV_SMEMB (6*PLANE*4)            // 208896 B
#define OUT_SMEMB ((4*PLANE+512)*4)      // 141312 B

// ---------------- scratch (device globals) ----------------
__device__ float g_Qu[NN*CC], g_Ku[NN*CC], g_Vu[NN*CC];
__device__ float g_Qi[NN*CC], g_Ki[NN*CC], g_Vi[NN*CC];
__device__ float g_agg_u[NN*CC], g_agg_i[NN*CC];
__device__ uint32_t g_Whi[4][CC*CC/2], g_Wlo[4][CC*CC/2];   // q,k,v,o
__device__ int g_ck_ui[TS], g_cv_ui[TS];
__device__ int g_ck_iu[TS], g_cv_iu[TS];
__device__ int g_rk_ui[TS], g_rk_iu[TS];
__device__ int g_deg_u[NN], g_deg_i[NN], g_indeg_u[NN], g_indeg_i[NN];
__device__ int g_off_i[NN+1], g_off_u[NN+1];
__device__ int g_cur_i[NN], g_cur_u[NN];
__device__ int g_csr_ui[EE], g_csr_iu[EE];   // src ids grouped by dst

// ---------------- helpers ----------------
__device__ __forceinline__ uint32_t smem_u32(const void* p){
  uint32_t a;
  asm("{ .reg .u64 t; cvta.to.shared.u64 t, %1; cvt.u32.u64 %0, t; }" : "=r"(a) : "l"(p));
  return a;
}
__device__ __forceinline__ void bsplit(float a, float b, uint32_t& hi, uint32_t& lo){
  __nv_bfloat16 ha = __float2bfloat16(a), hb = __float2bfloat16(b);
  float ra = a - __bfloat162float(ha);
  float rb = b - __bfloat162float(hb);
  __nv_bfloat16 la = __float2bfloat16(ra), lb = __float2bfloat16(rb);
  hi = ((uint32_t)__bfloat16_as_ushort(hb) << 16) | (uint32_t)__bfloat16_as_ushort(ha);
  lo = ((uint32_t)__bfloat16_as_ushort(lb) << 16) | (uint32_t)__bfloat16_as_ushort(la);
}
__device__ __forceinline__ void mma_bf16(float* c,
    uint32_t a0, uint32_t a1, uint32_t a2, uint32_t a3,
    uint32_t b0, uint32_t b1){
  asm volatile("mma.sync.aligned.m16n8k16.row.col.f32.bf16.bf16.f32 "
    "{%0,%1,%2,%3}, {%4,%5,%6,%7}, {%8,%9}, {%0,%1,%2,%3};"
    : "+f"(c[0]), "+f"(c[1]), "+f"(c[2]), "+f"(c[3])
    : "r"(a0), "r"(a1), "r"(a2), "r"(a3), "r"(b0), "r"(b1));
}
__device__ __forceinline__ void ldsm4(uint32_t* r, uint32_t addr){
  asm volatile("ldmatrix.sync.aligned.m8n8.x4.shared.b16 {%0,%1,%2,%3}, [%4];"
    : "=r"(r[0]), "=r"(r[1]), "=r"(r[2]), "=r"(r[3]) : "r"(addr));
}
#define CP_ASYNC16(dst, src) asm volatile("cp.async.cg.shared.global [%0], [%1], 16;" :: "r"(dst), "l"(src))
#define CP_COMMIT()  asm volatile("cp.async.commit_group;" ::: "memory")
#define CP_WAIT(n)   asm volatile("cp.async.wait_group %0;" :: "n"(n) : "memory")

__device__ __forceinline__ void cpb(uint32_t sb, int wbase, const uint32_t* __restrict__ gsrc){
  int tid = threadIdx.x;
  #pragma unroll
  for (int it = 0; it < 8; it++){
    int c = tid + it*256;
    int row = c >> 4, cw = (c & 15) * 4;
    CP_ASYNC16(sb + (uint32_t)(wbase + row*PITCH + cw)*4, gsrc + row*64 + cw);
  }
}

__device__ __forceinline__ void mma_core(uint32_t a_hi, uint32_t a_lo,
                                         uint32_t b_hi, uint32_t b_lo,
                                         float acc[2][8][4]){
  #pragma unroll
  for (int s = 0; s < 8; s++){
    uint32_t k2b = s*32;
    uint32_t ah[2][4], al[2][4];
    ldsm4(ah[0], a_hi + k2b);
    ldsm4(ah[1], a_hi + 16*PITCH*4 + k2b);
    ldsm4(al[0], a_lo + k2b);
    ldsm4(al[1], a_lo + 16*PITCH*4 + k2b);
    uint32_t bh[4][4], bl[4][4];
    #pragma unroll
    for (int p = 0; p < 4; p++){
      ldsm4(bh[p], b_hi + (uint32_t)p*16*PITCH*4 + k2b);
      ldsm4(bl[p], b_lo + (uint32_t)p*16*PITCH*4 + k2b);
    }
    #pragma unroll
    for (int p = 0; p < 4; p++)
      #pragma unroll
      for (int e = 0; e < 2; e++){
        int nt = p*2 + e;
        uint32_t b0h = bh[p][e*2], b1h = bh[p][e*2+1];
        uint32_t b0l = bl[p][e*2], b1l = bl[p][e*2+1];
        #pragma unroll
        for (int mt = 0; mt < 2; mt++){
          mma_bf16(acc[mt][nt], ah[mt][0],ah[mt][1],ah[mt][2],ah[mt][3], b0h, b1h);
          mma_bf16(acc[mt][nt], ah[mt][0],ah[mt][1],ah[mt][2],ah[mt][3], b0l, b1l);
          mma_bf16(acc[mt][nt], al[mt][0],al[mt][1],al[mt][2],al[mt][3], b0h, b1h);
        }
      }
  }
}

// ---------------- hash helpers ----------------
__device__ __forceinline__ unsigned hmix(int k){
  unsigned x = (unsigned)k; x *= 2654435761u; x ^= x >> 15; return x & TMASK;
}
__device__ __forceinline__ void hinsert_count(int* keys, int* vals, int key){
  unsigned slot = hmix(key);
  while (true){
    int prev = atomicCAS(&keys[slot], -1, key);
    if (prev == -1 || prev == key){ atomicAdd(&vals[slot], 1); return; }
    slot = (slot + 1) & TMASK;
  }
}
__device__ __forceinline__ void hinsert_set(int* keys, int key){
  unsigned slot = hmix(key);
  while (true){
    int prev = atomicCAS(&keys[slot], -1, key);
    if (prev == -1 || prev == key) return;
    slot = (slot + 1) & TMASK;
  }
}
__device__ __forceinline__ int hcount(const int* __restrict__ keys, const int* __restrict__ vals, int key){
  unsigned slot = hmix(key);
  while (true){
    int k = keys[slot];
    if (k == key) return vals[slot];
    if (k == -1) return 0;
    slot = (slot + 1) & TMASK;
  }
}
__device__ __forceinline__ bool hmember(const int* __restrict__ keys, int key){
  unsigned slot = hmix(key);
  while (true){
    int k = keys[slot];
    if (k == key) return true;
    if (k == -1) return false;
    slot = (slot + 1) & TMASK;
  }
}

// ---------------- init / build / wsplit / scan / scatter ----------------
__global__ void k_init(){
  int i = blockIdx.x*blockDim.x + threadIdx.x;
  int stride = gridDim.x*blockDim.x;
  for (int j=i;j<(int)TS;j+=stride){
    g_ck_ui[j]=-1; g_ck_iu[j]=-1; g_rk_ui[j]=-1; g_rk_iu[j]=-1;
    g_cv_ui[j]=0;  g_cv_iu[j]=0;
  }
  for (int j=i;j<NN;j+=stride){ g_deg_u[j]=0; g_deg_i[j]=0; g_indeg_u[j]=0; g_indeg_i[j]=0; }
}

__global__ void k_build(const int* __restrict__ eui, const int* __restrict__ eiu){
  int i = blockIdx.x*blockDim.x + threadIdx.x;
  if (i < EE){
    int su = eui[i], du = eui[EE+i];
    hinsert_count(g_ck_ui, g_cv_ui, su*NN + du);
    hinsert_set  (g_rk_iu, du*NN + su);
    atomicAdd(&g_deg_u[su],1); atomicAdd(&g_deg_i[du],1); atomicAdd(&g_indeg_i[du],1);
  } else if (i < 2*EE){
    int j = i - EE;
    int si = eiu[j], di = eiu[EE+j];
    hinsert_count(g_ck_iu, g_cv_iu, si*NN + di);
    hinsert_set  (g_rk_ui, di*NN + si);
    atomicAdd(&g_deg_i[si],1); atomicAdd(&g_deg_u[di],1); atomicAdd(&g_indeg_u[di],1);
  }
}

__global__ void k_wsplit(const float* __restrict__ Wq, const float* __restrict__ Wk,
                         const float* __restrict__ Wv, const float* __restrict__ Wo){
  const float* Ws[4] = {Wq, Wk, Wv, Wo};
  int m = blockIdx.y;
  int i = blockIdx.x*256 + threadIdx.x;
  float2 v = *(const float2*)(Ws[m] + i*2);
  uint32_t hi, lo; bsplit(v.x, v.y, hi, lo);
  g_Whi[m][i] = hi; g_Wlo[m][i] = lo;
}

// parallel exclusive prefix sum over indeg -> off, cur.  2 CTAs (one per relation), 1024 thr.
__global__ void k_scan2(){
  const int* indeg = blockIdx.x ? g_indeg_u : g_indeg_i;
  int* off = blockIdx.x ? g_off_u : g_off_i;
  int* cur = blockIdx.x ? g_cur_u : g_cur_i;
  __shared__ int wsum[32];
  __shared__ int woff[33];
  int tid = threadIdx.x, lane = tid & 31, wid = tid >> 5;
  const int per = 40;                    // 1024*40 >= NN
  int base = tid*per;
  int s = 0;
  #pragma unroll 8
  for (int j=0;j<per;j++){ int idx=base+j; if (idx<NN) s += indeg[idx]; }
  // warp inclusive scan
  int inc = s;
  #pragma unroll
  for (int o=1;o<32;o<<=1){
    int t = __shfl_up_sync(0xffffffffu, inc, o);
    if (lane >= o) inc += t;
  }
  if (lane == 31) wsum[wid] = inc;
  __syncthreads();
  if (wid == 0){
    int v = wsum[lane];
    int vi = v;
    #pragma unroll
    for (int o=1;o<32;o<<=1){
      int t = __shfl_up_sync(0xffffffffu, vi, o);
      if (lane >= o) vi += t;
    }
    woff[lane+1] = vi;
    if (lane == 0) woff[0] = 0;
  }
  __syncthreads();
  int run = woff[wid] + inc - s;         // exclusive prefix for this thread
  #pragma unroll 8
  for (int j=0;j<per;j++){
    int idx = base+j;
    if (idx<NN){ off[idx]=run; cur[idx]=run; run += indeg[idx]; }
  }
  if (tid == 1023) off[NN] = woff[32];
}

__global__ void k_scatter(const int* __restrict__ eui, const int* __restrict__ eiu){
  int i = blockIdx.x*blockDim.x + threadIdx.x;
  if (i < EE){
    int s = eui[i], d = eui[EE+i];
    int pos = atomicAdd(&g_cur_i[d], 1);
    g_csr_ui[pos] = s;
  } else if (i < 2*EE){
    int j = i - EE;
    int s = eiu[j], d = eiu[EE+j];
    int pos = atomicAdd(&g_cur_u[d], 1);
    g_csr_iu[pos] = s;
  }
}

// ---------------- fused QKV GEMMs ----------------
__global__ __launch_bounds__(256,1) void k_qkv3(
    const float* __restrict__ Xu, const float* __restrict__ Xi,
    float* __restrict__ Qu, float* __restrict__ Ku, float* __restrict__ Vu,
    float* __restrict__ Qi, float* __restrict__ Ki, float* __restrict__ Vi,
    const float* __restrict__ bq, const float* __restrict__ bk, const float* __restrict__ bv){
  extern __shared__ uint32_t sm[];
  uint32_t sb = smem_u32(sm);
  int tid = threadIdx.x, lane = tid & 31, wid = tid >> 5;
  int mw = wid & 3, nw = wid >> 2, tg = lane >> 2, tq = lane & 3;
  int row0 = blockIdx.x * MT;
  const float* X = blockIdx.y ? Xi : Xu;
  float* Ys[3];
  if (blockIdx.y == 0){ Ys[0]=Qu; Ys[1]=Ku; Ys[2]=Vu; }
  else               { Ys[0]=Qi; Ys[1]=Ki; Ys[2]=Vi; }
  const float* bs[3] = {bq, bk, bv};

  #pragma unroll
  for (int it = 0; it < 32; it++){
    int idx = tid + it*256;
    int row = idx >> 6, j = idx & 63;
    int gr = row0 + row;
    float2 v = make_float2(0.f, 0.f);
    if (gr < NN) v = *(const float2*)(X + (size_t)gr*CC + j*2);
    uint32_t hi, lo; bsplit(v.x, v.y, hi, lo);
    sm[AHI + row*PITCH + j] = hi;
    sm[ALO + row*PITCH + j] = lo;
  }

  cpb(sb, B0HI, g_Whi[0]); cpb(sb, B0LO, g_Wlo[0]); CP_COMMIT();

  uint32_t a_toff = (uint32_t)(((mw*32 + (lane&15))*PITCH + (lane>>4)*4))*4;
  uint32_t b_toff = (uint32_t)(((nw*64 + (lane&7) + (lane>>4)*8)*PITCH + ((lane>>3)&1)*4))*4;
  uint32_t a_hi = sb + (uint32_t)AHI*4 + a_toff;
  uint32_t a_lo = sb + (uint32_t)ALO*4 + a_toff;

  #pragma unroll
  for (int m = 0; m < 3; m++){
    if (m < 2){
      int wb_hi = ((m+1)&1) ? B1HI : B0HI;
      int wb_lo = ((m+1)&1) ? B1LO : B0LO;
      cpb(sb, wb_hi, g_Whi[m+1]); cpb(sb, wb_lo, g_Wlo[m+1]); CP_COMMIT();
      CP_WAIT(1);
    } else {
      CP_WAIT(0);
    }
    __syncthreads();

    float acc[2][8][4];
    #pragma unroll
    for (int a=0;a<2;a++)
      #pragma unroll
      for (int b=0;b<8;b++)
        #pragma unroll
        for (int c=0;c<4;c++) acc[a][b][c]=0.f;

    uint32_t b_hi = sb + (uint32_t)((m&1) ? B1HI : B0HI)*4 + b_toff;
    uint32_t b_lo = sb + (uint32_t)((m&1) ? B1LO : B0LO)*4 + b_toff;
    mma_core(a_hi, a_lo, b_hi, b_lo, acc);

    const float* bias = bs[m];
    float* Y = Ys[m];
    #pragma unroll
    for (int mt = 0; mt < 2; mt++){
      int r = row0 + mw*32 + mt*16 + tg;
      #pragma unroll
      for (int nt = 0; nt < 8; nt++){
        int col = nw*64 + nt*8 + tq*2;
        float2 bb = *(const float2*)(bias + col);
        if (r < NN)
          *(float2*)(Y + (size_t)r*CC + col) = make_float2(acc[mt][nt][0]+bb.x, acc[mt][nt][1]+bb.y);
        if (r + 8 < NN)
          *(float2*)(Y + (size_t)(r+8)*CC + col) = make_float2(acc[mt][nt][2]+bb.x, acc[mt][nt][3]+bb.y);
      }
    }
    __syncthreads();
  }
}

// ---------------- CSR aggregation: warp per destination, both relations ----------------
__global__ __launch_bounds__(256) void k_agg2(
    const float* __restrict__ Qi, const float* __restrict__ Ku, const float* __restrict__ Vu,
    const float* __restrict__ Qu, const float* __restrict__ Ki, const float* __restrict__ Vi,
    const float* __restrict__ t_user, const float* __restrict__ t_item,
    const float* __restrict__ hb, const float* __restrict__ beta2,
    const float* __restrict__ tau_raw,
    const float* __restrict__ gamma2, const float* __restrict__ delta2){
  int r = blockIdx.y;
  int d = blockIdx.x*8 + (threadIdx.x>>5);
  if (d >= NN) return;
  int lane = threadIdx.x & 31;
  int h = lane >> 3;
  const int* off   = r ? g_off_u  : g_off_i;
  const int* csrc  = r ? g_csr_iu : g_csr_ui;
  const float* Q   = r ? Qu : Qi;
  const float* K   = r ? Ki : Ku;
  const float* V   = r ? Vi : Vu;
  const float* ts  = r ? t_item : t_user;
  const float* tdv = r ? t_user : t_item;
  const int* ckeys = r ? g_ck_iu : g_ck_ui;
  const int* cvals = r ? g_cv_iu : g_cv_ui;
  const int* rkeys = r ? g_rk_iu : g_rk_ui;
  float* agg       = r ? g_agg_u : g_agg_i;

  int beg = off[d], end = off[d+1];
  float4 q = __ldg((const float4*)(Q + (size_t)d*CC) + lane);
  float hbh = hb[r*HH+h], bh = beta2[r*HH+h], gh = gamma2[r*HH+h], dh = delta2[r*HH+h];
  float traw = tau_raw[r];
  float tau = (traw > 20.f) ? traw : log1pf(expf(traw));
  tau += 1e-6f;
  float td = tdv[d];
  float4 acc = make_float4(0.f,0.f,0.f,0.f);
  float z = 0.f;
  for (int base = beg; base < end; base += 32){
    int m = end - base; if (m > 32) m = 32;
    int s = 0; float tl = 0.f, lc = 0.f, rec = 0.f;
    if (lane < m){
      s = csrc[base + lane];
      float dt = fabsf(td - ts[s]) + 1e-6f;
      tl = -log1pf(dt / tau);
      int pid = s*NN + d;
      lc = log1pf((float)(hcount(ckeys, cvals, pid) - 1));
      rec = hmember(rkeys, pid) ? 1.f : 0.f;
    }
    for (int j = 0; j < m; j++){
      int sj    = __shfl_sync(0xffffffffu, s,   j);
      float tlj = __shfl_sync(0xffffffffu, tl,  j);
      float lcj = __shfl_sync(0xffffffffu, lc,  j);
      float rcj = __shfl_sync(0xffffffffu, rec, j);
      float4 kk = __ldg((const float4*)(K + (size_t)sj*CC) + lane);
      float4 vv = __ldg((const float4*)(V + (size_t)sj*CC) + lane);
      float p = q.x*kk.x + q.y*kk.y + q.z*kk.z + q.w*kk.w;
      p += __shfl_xor_sync(0xffffffffu, p, 1);
      p += __shfl_xor_sync(0xffffffffu, p, 2);
      p += __shfl_xor_sync(0xffffffffu, p, 4);
      float sc = p*0.17677669529663687f + hbh + tlj*bh + lcj*gh + rcj*dh;
      float w = expf(sc);
      z += w;
      acc.x += vv.x*w; acc.y += vv.y*w; acc.z += vv.z*w; acc.w += vv.w*w;
    }
  }
  float inv = (z > 0.f) ? (1.f/z) : 0.f;
  *(float4*)(agg + (size_t)d*CC + lane*4) =
      make_float4(acc.x*inv, acc.y*inv, acc.z*inv, acc.w*inv);
}

// ---------------- epilogue: LN(agg@Wo^T + indeg*bo + deg + x), both node types ----------------
__global__ __launch_bounds__(256,1) void k_out_mma(
    const float* __restrict__ aggu, const float* __restrict__ aggi,
    const float* __restrict__ bias,
    const int* __restrict__ indegu, const int* __restrict__ indegi,
    const int* __restrict__ degu, const int* __restrict__ degi,
    const float* __restrict__ xu, const float* __restrict__ xi,
    float* __restrict__ out){
  extern __shared__ uint32_t sm[];
  uint32_t sb = smem_u32(sm);
  int tid = threadIdx.x, lane = tid & 31, wid = tid >> 5;
  int mw = wid & 3, nw = wid >> 2, tg = lane >> 2, tq = lane & 3;
  int row0 = blockIdx.x * MT;
  const float* agg; const int* indeg; const int* deg; const float* xres; float* o;
  if (blockIdx.y == 0){ agg=aggu; indeg=indegu; deg=degu; xres=xu; o=out; }
  else { agg=aggi; indeg=indegi; deg=degi; xres=xi; o=out + (size_t)NN*CC; }

  cpb(sb, B0HI, g_Whi[3]); cpb(sb, B0LO, g_Wlo[3]); CP_COMMIT();

  #pragma unroll
  for (int it = 0; it < 32; it++){
    int idx = tid + it*256;
    int row = idx >> 6, j = idx & 63;
    int gr = row0 + row;
    float2 v = make_float2(0.f, 0.f);
    if (gr < NN) v = *(const float2*)(agg + (size_t)gr*CC + j*2);
    uint32_t hi, lo; bsplit(v.x, v.y, hi, lo);
    sm[AHI + row*PITCH + j] = hi;
    sm[ALO + row*PITCH + j] = lo;
  }
  CP_WAIT(0);
  __syncthreads();

  uint32_t a_toff = (uint32_t)(((mw*32 + (lane&15))*PITCH + (lane>>4)*4))*4;
  uint32_t b_toff = (uint32_t)(((nw*64 + (lane&7) + (lane>>4)*8)*PITCH + ((lane>>3)&1)*4))*4;

  float acc[2][8][4];
  #pragma unroll
  for (int a=0;a<2;a++)
    #pragma unroll
    for (int b=0;b<8;b++)
      #pragma unroll
      for (int c=0;c<4;c++) acc[a][b][c]=0.f;

  mma_core(sb + (uint32_t)AHI*4 + a_toff, sb + (uint32_t)ALO*4 + a_toff,
           sb + (uint32_t)B0HI*4 + b_toff, sb + (uint32_t)B0LO*4 + b_toff, acc);

  float* reds = (float*)(sm + RED0);
  float* redq = (float*)(sm + RED0 + 256);

  float2 bb[8];
  #pragma unroll
  for (int nt = 0; nt < 8; nt++) bb[nt] = *(const float2*)(bias + nw*64 + nt*8 + tq*2);

  #pragma unroll
  for (int mt = 0; mt < 2; mt++){
    #pragma unroll
    for (int h = 0; h < 2; h++){
      int lr = mw*32 + mt*16 + tg + h*8;
      int grow = row0 + lr;
      float dg = 0.f, idg = 0.f;
      if (grow < NN){ dg = (float)deg[grow]; idg = (float)indeg[grow]; }
      float s = 0.f;
      #pragma unroll
      for (int nt = 0; nt < 8; nt++){
        int col = nw*64 + nt*8 + tq*2;
        float2 xr = make_float2(0.f, 0.f);
        if (grow < NN) xr = *(const float2*)(xres + (size_t)grow*CC + col);
        float v0 = acc[mt][nt][h*2+0] + bb[nt].x*idg + dg + xr.x;
        float v1 = acc[mt][nt][h*2+1] + bb[nt].y*idg + dg + xr.y;
        acc[mt][nt][h*2+0] = v0;
        acc[mt][nt][h*2+1] = v1;
        s += v0 + v1;
      }
      s += __shfl_xor_sync(0xffffffffu, s, 1);
      s += __shfl_xor_sync(0xffffffffu, s, 2);
      if (tq == 0) reds[lr*2 + nw] = s;
    }
  }
  __syncthreads();

  float mu[2][2];
  #pragma unroll
  for (int mt = 0; mt < 2; mt++)
    #pragma unroll
    for (int h = 0; h < 2; h++){
      int lr = mw*32 + mt*16 + tg + h*8;
      mu[mt][h] = (reds[lr*2] + reds[lr*2+1]) * (1.f/128.f);
    }

  #pragma unroll
  for (int mt = 0; mt < 2; mt++){
    #pragma unroll
    for (int h = 0; h < 2; h++){
      int lr = mw*32 + mt*16 + tg + h*8;
      float q = 0.f;
      #pragma unroll
      for (int nt = 0; nt < 8; nt++){
        float d0 = acc[mt][nt][h*2+0] - mu[mt][h];
        float d1 = acc[mt][nt][h*2+1] - mu[mt][h];
        q += d0*d0 + d1*d1;
      }
      q += __shfl_xor_sync(0xffffffffu, q, 1);
      q += __shfl_xor_sync(0xffffffffu, q, 2);
      if (tq == 0) redq[lr*2 + nw] = q;
    }
  }
  __syncthreads();

  #pragma unroll
  for (int mt = 0; mt < 2; mt++){
    #pragma unroll
    for (int h = 0; h < 2; h++){
      int lr = mw*32 + mt*16 + tg + h*8;
      int grow = row0 + lr;
      if (grow >= NN) continue;
      float var = (redq[lr*2] + redq[lr*2+1]) * (1.f/128.f);
      float rs = rsqrtf(var + 1e-5f);
      float m = mu[mt][h];
      #pragma unroll
      for (int nt = 0; nt < 8; nt++){
        int col = nw*64 + nt*8 + tq*2;
        *(float2*)(o + (size_t)grow*CC + col) =
          make_float2((acc[mt][nt][h*2+0]-m)*rs, (acc[mt][nt][h*2+1]-m)*rs);
      }
    }
  }
}

// ---------------- launch ----------------
extern "C" void kernel_launch(void* const* d_in, const int* in_sizes, int n_in,
                              void* d_out, int out_size){
  const float* x_user=(const float*)d_in[0];
  const float* x_item=(const float*)d_in[1];
  const float* t_user=(const float*)d_in[2];
  const float* t_item=(const float*)d_in[3];
  const int*   eui  =(const int*)  d_in[4];
  const int*   eiu  =(const int*)  d_in[5];
  const float* Wq=(const float*)d_in[6];  const float* bq=(const float*)d_in[7];
  const float* Wk=(const float*)d_in[8];  const float* bk=(const float*)d_in[9];
  const float* Wv=(const float*)d_in[10]; const float* bv=(const float*)d_in[11];
  const float* Wo=(const float*)d_in[12]; const float* bo=(const float*)d_in[13];
  const float* hb=(const float*)d_in[14];
  const float* tb=(const float*)d_in[15];
  const float* traw=(const float*)d_in[16];
  const float* gm=(const float*)d_in[17];
  const float* dr=(const float*)d_in[18];
  float* out=(float*)d_out;

  float *Qu,*Ku,*Vu,*Qi,*Ki,*Vi,*aggu,*aggi;
  int *degu,*degi,*idgu,*idgi;
  cudaGetSymbolAddress((void**)&Qu, g_Qu);
  cudaGetSymbolAddress((void**)&Ku, g_Ku);
  cudaGetSymbolAddress((void**)&Vu, g_Vu);
  cudaGetSymbolAddress((void**)&Qi, g_Qi);
  cudaGetSymbolAddress((void**)&Ki, g_Ki);
  cudaGetSymbolAddress((void**)&Vi, g_Vi);
  cudaGetSymbolAddress((void**)&aggu, g_agg_u);
  cudaGetSymbolAddress((void**)&aggi, g_agg_i);
  cudaGetSymbolAddress((void**)&degu, g_deg_u);
  cudaGetSymbolAddress((void**)&degi, g_deg_i);
  cudaGetSymbolAddress((void**)&idgu, g_indeg_u);
  cudaGetSymbolAddress((void**)&idgi, g_indeg_i);

  cudaFuncSetAttribute(k_qkv3,   cudaFuncAttributeMaxDynamicSharedMemorySize, QKV_SMEMB);
  cudaFuncSetAttribute(k_out_mma,cudaFuncAttributeMaxDynamicSharedMemorySize, OUT_SMEMB);

  k_init<<<1024,256>>>();
  k_build<<<(2*EE+255)/256,256>>>(eui, eiu);
  k_wsplit<<<dim3(32,4),256>>>(Wq, Wk, Wv, Wo);
  k_scan2<<<2,1024>>>();
  k_scatter<<<(2*EE+255)/256,256>>>(eui, eiu);

  k_qkv3<<<dim3(NBLK,2),256,QKV_SMEMB>>>(x_user, x_item, Qu,Ku,Vu, Qi,Ki,Vi, bq,bk,bv);

  // both relations in one launch (r = blockIdx.y: 0 = user->item, 1 = item->user)
  k_agg2<<<dim3((NN+7)/8,2),256>>>(Qi, Ku, Vu, Qu, Ki, Vi, t_user, t_item,
                                   hb, tb, traw, gm, dr);

  k_out_mma<<<dim3(NBLK,2),256,OUT_SMEMB>>>(aggu, aggi, bo,
                                            idgu, idgi, degu, degi,
                                            x_user, x_item, out);
}

// round 8
// speedup vs baseline: 2.0330x; 1.1937x over previous
#include <cuda_runtime.h>
#include <cuda_bf16.h>
#include <math.h>
#include <stdint.h>

#define NN 40000
#define CC 128
#define HH 4
#define EE 200000
#define TS (1u<<19)
#define TMASK (TS-1u)

#define MT 128
#define NBLK ((NN + MT - 1) / MT)        // 313
#define PITCH 68
#define PLANE (128*PITCH)                // 8704 words
#define AHI 0
#define ALO PLANE
#define B0HI (2*PLANE)
#define B0LO (3*PLANE)
#define B1HI (4*PLANE)
#define B1LO (5*PLANE)
#define RED0 (4*PLANE)                   // k_out only (reuses B1 space)
#define QKV_SMEMB (6*PLANE*4)            // 208896 B
#define OUT_SMEMB ((4*PLANE+1024)*4)
#define SCAN_SMEMB ((40960+1024)*4)      // 167936 B

// ---------------- scratch (device globals) ----------------
__device__ float g_Qu[NN*CC], g_Ku[NN*CC], g_Vu[NN*CC];
__device__ float g_Qi[NN*CC], g_Ki[NN*CC], g_Vi[NN*CC];
__device__ float g_agg_u[NN*CC], g_agg_i[NN*CC];
__device__ uint32_t g_Whi[4][CC*CC/2], g_Wlo[4][CC*CC/2];   // q,k,v,o
__device__ int g_ck_ui[TS], g_cv_ui[TS];
__device__ int g_ck_iu[TS], g_cv_iu[TS];
__device__ int g_rk_ui[TS], g_rk_iu[TS];
__device__ int g_deg_u[NN], g_deg_i[NN], g_indeg_u[NN], g_indeg_i[NN];
__device__ int g_off_i[NN+1], g_off_u[NN+1];
__device__ int g_cur_i[NN], g_cur_u[NN];
__device__ int g_csr_ui[EE], g_csr_iu[EE];   // src ids grouped by dst

// ---------------- helpers ----------------
__device__ __forceinline__ uint32_t smem_u32(const void* p){
  uint32_t a;
  asm("{ .reg .u64 t; cvta.to.shared.u64 t, %1; cvt.u32.u64 %0, t; }" : "=r"(a) : "l"(p));
  return a;
}
__device__ __forceinline__ void bsplit(float a, float b, uint32_t& hi, uint32_t& lo){
  __nv_bfloat16 ha = __float2bfloat16(a), hb = __float2bfloat16(b);
  float ra = a - __bfloat162float(ha);
  float rb = b - __bfloat162float(hb);
  __nv_bfloat16 la = __float2bfloat16(ra), lb = __float2bfloat16(rb);
  hi = ((uint32_t)__bfloat16_as_ushort(hb) << 16) | (uint32_t)__bfloat16_as_ushort(ha);
  lo = ((uint32_t)__bfloat16_as_ushort(lb) << 16) | (uint32_t)__bfloat16_as_ushort(la);
}
__device__ __forceinline__ void mma_bf16(float* c,
    uint32_t a0, uint32_t a1, uint32_t a2, uint32_t a3,
    uint32_t b0, uint32_t b1){
  asm volatile("mma.sync.aligned.m16n8k16.row.col.f32.bf16.bf16.f32 "
    "{%0,%1,%2,%3}, {%4,%5,%6,%7}, {%8,%9}, {%0,%1,%2,%3};"
    : "+f"(c[0]), "+f"(c[1]), "+f"(c[2]), "+f"(c[3])
    : "r"(a0), "r"(a1), "r"(a2), "r"(a3), "r"(b0), "r"(b1));
}
__device__ __forceinline__ void ldsm4(uint32_t* r, uint32_t addr){
  asm volatile("ldmatrix.sync.aligned.m8n8.x4.shared.b16 {%0,%1,%2,%3}, [%4];"
    : "=r"(r[0]), "=r"(r[1]), "=r"(r[2]), "=r"(r[3]) : "r"(addr));
}
#define CP_ASYNC16(dst, src) asm volatile("cp.async.cg.shared.global [%0], [%1], 16;" :: "r"(dst), "l"(src))
#define CP_COMMIT()  asm volatile("cp.async.commit_group;" ::: "memory")
#define CP_WAIT(n)   asm volatile("cp.async.wait_group %0;" :: "n"(n) : "memory")

// copy 128x64-word plane (row-major) to smem; 512 threads
__device__ __forceinline__ void cpb(uint32_t sb, int wbase, const uint32_t* __restrict__ gsrc){
  int tid = threadIdx.x;
  #pragma unroll
  for (int it = 0; it < 4; it++){
    int c = tid + it*512;
    int row = c >> 4, cw = (c & 15) * 4;
    CP_ASYNC16(sb + (uint32_t)(wbase + row*PITCH + cw)*4, gsrc + row*64 + cw);
  }
}

// core: acc[2][4][4] += A @ B^T; warp owns 32 rows x 32 cols; bf16 3-term split
__device__ __forceinline__ void mma_core(uint32_t a_hi, uint32_t a_lo,
                                         uint32_t b_hi, uint32_t b_lo,
                                         float acc[2][4][4]){
  #pragma unroll
  for (int s = 0; s < 8; s++){
    uint32_t k2b = s*32;
    uint32_t ah[2][4], al[2][4];
    ldsm4(ah[0], a_hi + k2b);
    ldsm4(ah[1], a_hi + 16*PITCH*4 + k2b);
    ldsm4(al[0], a_lo + k2b);
    ldsm4(al[1], a_lo + 16*PITCH*4 + k2b);
    uint32_t bh[2][4], bl[2][4];
    #pragma unroll
    for (int p = 0; p < 2; p++){
      ldsm4(bh[p], b_hi + (uint32_t)p*16*PITCH*4 + k2b);
      ldsm4(bl[p], b_lo + (uint32_t)p*16*PITCH*4 + k2b);
    }
    #pragma unroll
    for (int p = 0; p < 2; p++)
      #pragma unroll
      for (int e = 0; e < 2; e++){
        int nt = p*2 + e;
        uint32_t b0h = bh[p][e*2], b1h = bh[p][e*2+1];
        uint32_t b0l = bl[p][e*2], b1l = bl[p][e*2+1];
        #pragma unroll
        for (int mt = 0; mt < 2; mt++){
          mma_bf16(acc[mt][nt], ah[mt][0],ah[mt][1],ah[mt][2],ah[mt][3], b0h, b1h);
          mma_bf16(acc[mt][nt], ah[mt][0],ah[mt][1],ah[mt][2],ah[mt][3], b0l, b1l);
          mma_bf16(acc[mt][nt], al[mt][0],al[mt][1],al[mt][2],al[mt][3], b0h, b1h);
        }
      }
  }
}

// ---------------- hash helpers ----------------
__device__ __forceinline__ unsigned hmix(int k){
  unsigned x = (unsigned)k; x *= 2654435761u; x ^= x >> 15; return x & TMASK;
}
__device__ __forceinline__ void hinsert_count(int* keys, int* vals, int key){
  unsigned slot = hmix(key);
  while (true){
    int prev = atomicCAS(&keys[slot], -1, key);
    if (prev == -1 || prev == key){ atomicAdd(&vals[slot], 1); return; }
    slot = (slot + 1) & TMASK;
  }
}
__device__ __forceinline__ void hinsert_set(int* keys, int key){
  unsigned slot = hmix(key);
  while (true){
    int prev = atomicCAS(&keys[slot], -1, key);
    if (prev == -1 || prev == key) return;
    slot = (slot + 1) & TMASK;
  }
}
__device__ __forceinline__ int hcount(const int* __restrict__ keys, const int* __restrict__ vals, int key){
  unsigned slot = hmix(key);
  while (true){
    int k = keys[slot];
    if (k == key) return vals[slot];
    if (k == -1) return 0;
    slot = (slot + 1) & TMASK;
  }
}
__device__ __forceinline__ bool hmember(const int* __restrict__ keys, int key){
  unsigned slot = hmix(key);
  while (true){
    int k = keys[slot];
    if (k == key) return true;
    if (k == -1) return false;
    slot = (slot + 1) & TMASK;
  }
}

// ---------------- init / build / wsplit / scan / scatter ----------------
__global__ void k_init(){
  int i = blockIdx.x*blockDim.x + threadIdx.x;
  int stride = gridDim.x*blockDim.x;
  for (int j=i;j<(int)TS;j+=stride){
    g_ck_ui[j]=-1; g_ck_iu[j]=-1; g_rk_ui[j]=-1; g_rk_iu[j]=-1;
    g_cv_ui[j]=0;  g_cv_iu[j]=0;
  }
  for (int j=i;j<NN;j+=stride){ g_deg_u[j]=0; g_deg_i[j]=0; g_indeg_u[j]=0; g_indeg_i[j]=0; }
}

__global__ void k_build(const int* __restrict__ eui, const int* __restrict__ eiu){
  int i = blockIdx.x*blockDim.x + threadIdx.x;
  if (i < EE){
    int su = eui[i], du = eui[EE+i];
    hinsert_count(g_ck_ui, g_cv_ui, su*NN + du);
    hinsert_set  (g_rk_iu, du*NN + su);
    atomicAdd(&g_deg_u[su],1); atomicAdd(&g_deg_i[du],1); atomicAdd(&g_indeg_i[du],1);
  } else if (i < 2*EE){
    int j = i - EE;
    int si = eiu[j], di = eiu[EE+j];
    hinsert_count(g_ck_iu, g_cv_iu, si*NN + di);
    hinsert_set  (g_rk_ui, di*NN + si);
    atomicAdd(&g_deg_i[si],1); atomicAdd(&g_deg_u[di],1); atomicAdd(&g_indeg_u[di],1);
  }
}

__global__ void k_wsplit(const float* __restrict__ Wq, const float* __restrict__ Wk,
                         const float* __restrict__ Wv, const float* __restrict__ Wo){
  const float* Ws[4] = {Wq, Wk, Wv, Wo};
  int m = blockIdx.y;
  int i = blockIdx.x*256 + threadIdx.x;
  float2 v = *(const float2*)(Ws[m] + i*2);
  uint32_t hi, lo; bsplit(v.x, v.y, hi, lo);
  g_Whi[m][i] = hi; g_Wlo[m][i] = lo;
}

// coalesced smem-staged exclusive prefix sum.  2 CTAs (one per relation), 1024 thr.
__global__ void k_scan2(){
  extern __shared__ int ss[];          // [40960] values + [1024] thread bases
  int* basep = ss + 40960;
  __shared__ int wsum[32];
  __shared__ int woff[33];
  const int* indeg = blockIdx.x ? g_indeg_u : g_indeg_i;
  int* off = blockIdx.x ? g_off_u : g_off_i;
  int* cur = blockIdx.x ? g_cur_u : g_cur_i;
  int tid = threadIdx.x, lane = tid & 31, wid = tid >> 5;
  // coalesced load into smem
  #pragma unroll
  for (int it = 0; it < 40; it++){
    int i = it*1024 + tid;
    ss[i] = (i < NN) ? indeg[i] : 0;
  }
  __syncthreads();
  // per-thread serial exclusive scan in smem
  int s = 0, b = tid*40;
  #pragma unroll 8
  for (int j = 0; j < 40; j++){ int t = ss[b+j]; ss[b+j] = s; s += t; }
  // hierarchical scan of per-thread sums
  int inc = s;
  #pragma unroll
  for (int o=1;o<32;o<<=1){
    int t = __shfl_up_sync(0xffffffffu, inc, o);
    if (lane >= o) inc += t;
  }
  if (lane == 31) wsum[wid] = inc;
  __syncthreads();
  if (wid == 0){
    int vi = wsum[lane];
    #pragma unroll
    for (int o=1;o<32;o<<=1){
      int t = __shfl_up_sync(0xffffffffu, vi, o);
      if (lane >= o) vi += t;
    }
    woff[lane+1] = vi;
    if (lane == 0) woff[0] = 0;
  }
  __syncthreads();
  basep[tid] = woff[wid] + inc - s;
  __syncthreads();
  // coalesced write-out
  #pragma unroll
  for (int it = 0; it < 40; it++){
    int i = it*1024 + tid;
    if (i < NN){
      int v = ss[i] + basep[i/40];
      off[i] = v; cur[i] = v;
    }
  }
  if (tid == 0) off[NN] = woff[32];
}

__global__ void k_scatter(const int* __restrict__ eui, const int* __restrict__ eiu){
  int i = blockIdx.x*blockDim.x + threadIdx.x;
  if (i < EE){
    int s = eui[i], d = eui[EE+i];
    int pos = atomicAdd(&g_cur_i[d], 1);
    g_csr_ui[pos] = s;
  } else if (i < 2*EE){
    int j = i - EE;
    int s = eiu[j], d = eiu[EE+j];
    int pos = atomicAdd(&g_cur_u[d], 1);
    g_csr_iu[pos] = s;
  }
}

// ---------------- fused QKV GEMMs (512 threads, 4x4 warp grid) ----------------
__global__ __launch_bounds__(512,1) void k_qkv3(
    const float* __restrict__ Xu, const float* __restrict__ Xi,
    float* __restrict__ Qu, float* __restrict__ Ku, float* __restrict__ Vu,
    float* __restrict__ Qi, float* __restrict__ Ki, float* __restrict__ Vi,
    const float* __restrict__ bq, const float* __restrict__ bk, const float* __restrict__ bv){
  extern __shared__ uint32_t sm[];
  uint32_t sb = smem_u32(sm);
  int tid = threadIdx.x, lane = tid & 31, wid = tid >> 5;
  int mw = wid & 3, nw = wid >> 2, tg = lane >> 2, tq = lane & 3;
  int row0 = blockIdx.x * MT;
  const float* X = blockIdx.y ? Xi : Xu;
  float* Ys[3];
  if (blockIdx.y == 0){ Ys[0]=Qu; Ys[1]=Ku; Ys[2]=Vu; }
  else               { Ys[0]=Qi; Ys[1]=Ki; Ys[2]=Vi; }
  const float* bs[3] = {bq, bk, bv};

  #pragma unroll
  for (int it = 0; it < 16; it++){
    int idx = tid + it*512;
    int row = idx >> 6, j = idx & 63;
    int gr = row0 + row;
    float2 v = make_float2(0.f, 0.f);
    if (gr < NN) v = *(const float2*)(X + (size_t)gr*CC + j*2);
    uint32_t hi, lo; bsplit(v.x, v.y, hi, lo);
    sm[AHI + row*PITCH + j] = hi;
    sm[ALO + row*PITCH + j] = lo;
  }

  cpb(sb, B0HI, g_Whi[0]); cpb(sb, B0LO, g_Wlo[0]); CP_COMMIT();

  uint32_t a_toff = (uint32_t)(((mw*32 + (lane&15))*PITCH + (lane>>4)*4))*4;
  uint32_t b_toff = (uint32_t)(((nw*32 + (lane&7) + (lane>>4)*8)*PITCH + ((lane>>3)&1)*4))*4;
  uint32_t a_hi = sb + (uint32_t)AHI*4 + a_toff;
  uint32_t a_lo = sb + (uint32_t)ALO*4 + a_toff;

  #pragma unroll
  for (int m = 0; m < 3; m++){
    if (m < 2){
      int wb_hi = ((m+1)&1) ? B1HI : B0HI;
      int wb_lo = ((m+1)&1) ? B1LO : B0LO;
      cpb(sb, wb_hi, g_Whi[m+1]); cpb(sb, wb_lo, g_Wlo[m+1]); CP_COMMIT();
      CP_WAIT(1);
    } else {
      CP_WAIT(0);
    }
    __syncthreads();

    float acc[2][4][4];
    #pragma unroll
    for (int a=0;a<2;a++)
      #pragma unroll
      for (int b=0;b<4;b++)
        #pragma unroll
        for (int c=0;c<4;c++) acc[a][b][c]=0.f;

    uint32_t b_hi = sb + (uint32_t)((m&1) ? B1HI : B0HI)*4 + b_toff;
    uint32_t b_lo = sb + (uint32_t)((m&1) ? B1LO : B0LO)*4 + b_toff;
    mma_core(a_hi, a_lo, b_hi, b_lo, acc);

    const float* bias = bs[m];
    float* Y = Ys[m];
    #pragma unroll
    for (int mt = 0; mt < 2; mt++){
      int r = row0 + mw*32 + mt*16 + tg;
      #pragma unroll
      for (int nt = 0; nt < 4; nt++){
        int col = nw*32 + nt*8 + tq*2;
        float2 bb = *(const float2*)(bias + col);
        if (r < NN)
          *(float2*)(Y + (size_t)r*CC + col) = make_float2(acc[mt][nt][0]+bb.x, acc[mt][nt][1]+bb.y);
        if (r + 8 < NN)
          *(float2*)(Y + (size_t)(r+8)*CC + col) = make_float2(acc[mt][nt][2]+bb.x, acc[mt][nt][3]+bb.y);
      }
    }
    __syncthreads();
  }
}

// ---------------- CSR aggregation: warp per destination, both relations ----------------
__global__ __launch_bounds__(256) void k_agg2(
    const float* __restrict__ Qi, const float* __restrict__ Ku, const float* __restrict__ Vu,
    const float* __restrict__ Qu, const float* __restrict__ Ki, const float* __restrict__ Vi,
    const float* __restrict__ t_user, const float* __restrict__ t_item,
    const float* __restrict__ hb, const float* __restrict__ beta2,
    const float* __restrict__ tau_raw,
    const float* __restrict__ gamma2, const float* __restrict__ delta2){
  int r = blockIdx.y;
  int d = blockIdx.x*8 + (threadIdx.x>>5);
  if (d >= NN) return;
  int lane = threadIdx.x & 31;
  int h = lane >> 3;
  const int* off   = r ? g_off_u  : g_off_i;
  const int* csrc  = r ? g_csr_iu : g_csr_ui;
  const float* Q   = r ? Qu : Qi;
  const float* K   = r ? Ki : Ku;
  const float* V   = r ? Vi : Vu;
  const float* ts  = r ? t_item : t_user;
  const float* tdv = r ? t_user : t_item;
  const int* ckeys = r ? g_ck_iu : g_ck_ui;
  const int* cvals = r ? g_cv_iu : g_cv_ui;
  const int* rkeys = r ? g_rk_iu : g_rk_ui;
  float* agg       = r ? g_agg_u : g_agg_i;

  int beg = off[d], end = off[d+1];
  float4 q = __ldg((const float4*)(Q + (size_t)d*CC) + lane);
  float hbh = hb[r*HH+h], bh = beta2[r*HH+h], gh = gamma2[r*HH+h], dh = delta2[r*HH+h];
  float traw = tau_raw[r];
  float tau = (traw > 20.f) ? traw : log1pf(expf(traw));
  tau += 1e-6f;
  float td = tdv[d];
  float4 acc = make_float4(0.f,0.f,0.f,0.f);
  float z = 0.f;
  for (int base = beg; base < end; base += 32){
    int m = end - base; if (m > 32) m = 32;
    int s = 0; float tl = 0.f, lc = 0.f, rec = 0.f;
    if (lane < m){
      s = csrc[base + lane];
      float dt = fabsf(td - ts[s]) + 1e-6f;
      tl = -log1pf(dt / tau);
      int pid = s*NN + d;
      lc = log1pf((float)(hcount(ckeys, cvals, pid) - 1));
      rec = hmember(rkeys, pid) ? 1.f : 0.f;
    }
    for (int j = 0; j < m; j++){
      int sj    = __shfl_sync(0xffffffffu, s,   j);
      float tlj = __shfl_sync(0xffffffffu, tl,  j);
      float lcj = __shfl_sync(0xffffffffu, lc,  j);
      float rcj = __shfl_sync(0xffffffffu, rec, j);
      float4 kk = __ldg((const float4*)(K + (size_t)sj*CC) + lane);
      float4 vv = __ldg((const float4*)(V + (size_t)sj*CC) + lane);
      float p = q.x*kk.x + q.y*kk.y + q.z*kk.z + q.w*kk.w;
      p += __shfl_xor_sync(0xffffffffu, p, 1);
      p += __shfl_xor_sync(0xffffffffu, p, 2);
      p += __shfl_xor_sync(0xffffffffu, p, 4);
      float sc = p*0.17677669529663687f + hbh + tlj*bh + lcj*gh + rcj*dh;
      float w = expf(sc);
      z += w;
      acc.x += vv.x*w; acc.y += vv.y*w; acc.z += vv.z*w; acc.w += vv.w*w;
    }
  }
  float inv = (z > 0.f) ? (1.f/z) : 0.f;
  *(float4*)(agg + (size_t)d*CC + lane*4) =
      make_float4(acc.x*inv, acc.y*inv, acc.z*inv, acc.w*inv);
}

// ---------------- epilogue (512 threads): LN(agg@Wo^T + indeg*bo + deg + x) ----------------
__global__ __launch_bounds__(512,1) void k_out_mma(
    const float* __restrict__ aggu, const float* __restrict__ aggi,
    const float* __restrict__ bias,
    const int* __restrict__ indegu, const int* __restrict__ indegi,
    const int* __restrict__ degu, const int* __restrict__ degi,
    const float* __restrict__ xu, const float* __restrict__ xi,
    float* __restrict__ out){
  extern __shared__ uint32_t sm[];
  uint32_t sb = smem_u32(sm);
  int tid = threadIdx.x, lane = tid & 31, wid = tid >> 5;
  int mw = wid & 3, nw = wid >> 2, tg = lane >> 2, tq = lane & 3;
  int row0 = blockIdx.x * MT;
  const float* agg; const int* indeg; const int* deg; const float* xres; float* o;
  if (blockIdx.y == 0){ agg=aggu; indeg=indegu; deg=degu; xres=xu; o=out; }
  else { agg=aggi; indeg=indegi; deg=degi; xres=xi; o=out + (size_t)NN*CC; }

  cpb(sb, B0HI, g_Whi[3]); cpb(sb, B0LO, g_Wlo[3]); CP_COMMIT();

  #pragma unroll
  for (int it = 0; it < 16; it++){
    int idx = tid + it*512;
    int row = idx >> 6, j = idx & 63;
    int gr = row0 + row;
    float2 v = make_float2(0.f, 0.f);
    if (gr < NN) v = *(const float2*)(agg + (size_t)gr*CC + j*2);
    uint32_t hi, lo; bsplit(v.x, v.y, hi, lo);
    sm[AHI + row*PITCH + j] = hi;
    sm[ALO + row*PITCH + j] = lo;
  }
  CP_WAIT(0);
  __syncthreads();

  uint32_t a_toff = (uint32_t)(((mw*32 + (lane&15))*PITCH + (lane>>4)*4))*4;
  uint32_t b_toff = (uint32_t)(((nw*32 + (lane&7) + (lane>>4)*8)*PITCH + ((lane>>3)&1)*4))*4;

  float acc[2][4][4];
  #pragma unroll
  for (int a=0;a<2;a++)
    #pragma unroll
    for (int b=0;b<4;b++)
      #pragma unroll
      for (int c=0;c<4;c++) acc[a][b][c]=0.f;

  mma_core(sb + (uint32_t)AHI*4 + a_toff, sb + (uint32_t)ALO*4 + a_toff,
           sb + (uint32_t)B0HI*4 + b_toff, sb + (uint32_t)B0LO*4 + b_toff, acc);

  float* reds = (float*)(sm + RED0);          // 512 floats
  float* redq = (float*)(sm + RED0 + 512);    // 512 floats

  float2 bb[4];
  #pragma unroll
  for (int nt = 0; nt < 4; nt++) bb[nt] = *(const float2*)(bias + nw*32 + nt*8 + tq*2);

  #pragma unroll
  for (int mt = 0; mt < 2; mt++){
    #pragma unroll
    for (int h = 0; h < 2; h++){
      int lr = mw*32 + mt*16 + tg + h*8;
      int grow = row0 + lr;
      float dg = 0.f, idg = 0.f;
      if (grow < NN){ dg = (float)deg[grow]; idg = (float)indeg[grow]; }
      float s = 0.f;
      #pragma unroll
      for (int nt = 0; nt < 4; nt++){
        int col = nw*32 + nt*8 + tq*2;
        float2 xr = make_float2(0.f, 0.f);
        if (grow < NN) xr = *(const float2*)(xres + (size_t)grow*CC + col);
        float v0 = acc[mt][nt][h*2+0] + bb[nt].x*idg + dg + xr.x;
        float v1 = acc[mt][nt][h*2+1] + bb[nt].y*idg + dg + xr.y;
        acc[mt][nt][h*2+0] = v0;
        acc[mt][nt][h*2+1] = v1;
        s += v0 + v1;
      }
      s += __shfl_xor_sync(0xffffffffu, s, 1);
      s += __shfl_xor_sync(0xffffffffu, s, 2);
      if (tq == 0) reds[lr*4 + nw] = s;
    }
  }
  __syncthreads();

  float mu[2][2];
  #pragma unroll
  for (int mt = 0; mt < 2; mt++)
    #pragma unroll
    for (int h = 0; h < 2; h++){
      int lr = mw*32 + mt*16 + tg + h*8;
      mu[mt][h] = (reds[lr*4] + reds[lr*4+1] + reds[lr*4+2] + reds[lr*4+3]) * (1.f/128.f);
    }

  #pragma unroll
  for (int mt = 0; mt < 2; mt++){
    #pragma unroll
    for (int h = 0; h < 2; h++){
      int lr = mw*32 + mt*16 + tg + h*8;
      float q = 0.f;
      #pragma unroll
      for (int nt = 0; nt < 4; nt++){
        float d0 = acc[mt][nt][h*2+0] - mu[mt][h];
        float d1 = acc[mt][nt][h*2+1] - mu[mt][h];
        q += d0*d0 + d1*d1;
      }
      q += __shfl_xor_sync(0xffffffffu, q, 1);
      q += __shfl_xor_sync(0xffffffffu, q, 2);
      if (tq == 0) redq[lr*4 + nw] = q;
    }
  }
  __syncthreads();

  #pragma unroll
  for (int mt = 0; mt < 2; mt++){
    #pragma unroll
    for (int h = 0; h < 2; h++){
      int lr = mw*32 + mt*16 + tg + h*8;
      int grow = row0 + lr;
      if (grow >= NN) continue;
      float var = (redq[lr*4] + redq[lr*4+1] + redq[lr*4+2] + redq[lr*4+3]) * (1.f/128.f);
      float rs = rsqrtf(var + 1e-5f);
      float m = mu[mt][h];
      #pragma unroll
      for (int nt = 0; nt < 4; nt++){
        int col = nw*32 + nt*8 + tq*2;
        *(float2*)(o + (size_t)grow*CC + col) =
          make_float2((acc[mt][nt][h*2+0]-m)*rs, (acc[mt][nt][h*2+1]-m)*rs);
      }
    }
  }
}

// ---------------- launch ----------------
extern "C" void kernel_launch(void* const* d_in, const int* in_sizes, int n_in,
                              void* d_out, int out_size){
  const float* x_user=(const float*)d_in[0];
  const float* x_item=(const float*)d_in[1];
  const float* t_user=(const float*)d_in[2];
  const float* t_item=(const float*)d_in[3];
  const int*   eui  =(const int*)  d_in[4];
  const int*   eiu  =(const int*)  d_in[5];
  const float* Wq=(const float*)d_in[6];  const float* bq=(const float*)d_in[7];
  const float* Wk=(const float*)d_in[8];  const float* bk=(const float*)d_in[9];
  const float* Wv=(const float*)d_in[10]; const float* bv=(const float*)d_in[11];
  const float* Wo=(const float*)d_in[12]; const float* bo=(const float*)d_in[13];
  const float* hb=(const float*)d_in[14];
  const float* tb=(const float*)d_in[15];
  const float* traw=(const float*)d_in[16];
  const float* gm=(const float*)d_in[17];
  const float* dr=(const float*)d_in[18];
  float* out=(float*)d_out;

  float *Qu,*Ku,*Vu,*Qi,*Ki,*Vi,*aggu,*aggi;
  int *degu,*degi,*idgu,*idgi;
  cudaGetSymbolAddress((void**)&Qu, g_Qu);
  cudaGetSymbolAddress((void**)&Ku, g_Ku);
  cudaGetSymbolAddress((void**)&Vu, g_Vu);
  cudaGetSymbolAddress((void**)&Qi, g_Qi);
  cudaGetSymbolAddress((void**)&Ki, g_Ki);
  cudaGetSymbolAddress((void**)&Vi, g_Vi);
  cudaGetSymbolAddress((void**)&aggu, g_agg_u);
  cudaGetSymbolAddress((void**)&aggi, g_agg_i);
  cudaGetSymbolAddress((void**)&degu, g_deg_u);
  cudaGetSymbolAddress((void**)&degi, g_deg_i);
  cudaGetSymbolAddress((void**)&idgu, g_indeg_u);
  cudaGetSymbolAddress((void**)&idgi, g_indeg_i);

  cudaFuncSetAttribute(k_qkv3,   cudaFuncAttributeMaxDynamicSharedMemorySize, QKV_SMEMB);
  cudaFuncSetAttribute(k_out_mma,cudaFuncAttributeMaxDynamicSharedMemorySize, OUT_SMEMB);
  cudaFuncSetAttribute(k_scan2,  cudaFuncAttributeMaxDynamicSharedMemorySize, SCAN_SMEMB);

  k_init<<<1024,256>>>();
  k_build<<<(2*EE+255)/256,256>>>(eui, eiu);
  k_wsplit<<<dim3(32,4),256>>>(Wq, Wk, Wv, Wo);
  k_scan2<<<2,1024,SCAN_SMEMB>>>();
  k_scatter<<<(2*EE+255)/256,256>>>(eui, eiu);

  k_qkv3<<<dim3(NBLK,2),512,QKV_SMEMB>>>(x_user, x_item, Qu,Ku,Vu, Qi,Ki,Vi, bq,bk,bv);

  // both relations in one launch (r = blockIdx.y: 0 = user->item, 1 = item->user)
  k_agg2<<<dim3((NN+7)/8,2),256>>>(Qi, Ku, Vu, Qu, Ki, Vi, t_user, t_item,
                                   hb, tb, traw, gm, dr);

  k_out_mma<<<dim3(NBLK,2),512,OUT_SMEMB>>>(aggu, aggi, bo,
                                            idgu, idgi, degu, degi,
                                            x_user, x_item, out);
}

// round 9
// speedup vs baseline: 2.2262x; 1.0950x over previous
#include <cuda_runtime.h>
#include <cuda_bf16.h>
#include <math.h>
#include <stdint.h>

#define NN 40000
#define CC 128
#define HH 4
#define EE 200000
#define TS (1u<<19)
#define TMASK (TS-1u)

#define MT 128
#define NBLK ((NN + MT - 1) / MT)        // 313
#define PITCH 68
#define PLANE (128*PITCH)                // 8704 words
#define AHI 0
#define ALO PLANE
#define B0HI (2*PLANE)
#define B0LO (3*PLANE)
#define B1HI (4*PLANE)
#define B1LO (5*PLANE)
#define RED0 (4*PLANE)                   // k_out only (reuses B1 space)
#define QKV_SMEMB (6*PLANE*4)            // 208896 B
#define OUT_SMEMB ((4*PLANE+1024)*4)
#define SCAN_SMEMB ((40960+1024)*4)      // 167936 B

// ---------------- scratch (device globals) ----------------
__device__ float g_Qu[NN*CC], g_Ku[NN*CC], g_Vu[NN*CC];
__device__ float g_Qi[NN*CC], g_Ki[NN*CC], g_Vi[NN*CC];
__device__ float g_agg_u[NN*CC], g_agg_i[NN*CC];
__device__ uint32_t g_Whi[4][CC*CC/2], g_Wlo[4][CC*CC/2];   // q,k,v,o
__device__ int g_ck_ui[TS], g_cv_ui[TS];
__device__ int g_ck_iu[TS], g_cv_iu[TS];
__device__ int g_rk_ui[TS], g_rk_iu[TS];
__device__ int g_deg_u[NN], g_deg_i[NN], g_indeg_u[NN], g_indeg_i[NN];
__device__ int g_off_i[NN+1], g_off_u[NN+1];
__device__ int g_cur_i[NN], g_cur_u[NN];
__device__ int g_csr_ui[EE], g_csr_iu[EE];   // src ids grouped by dst

// ---------------- helpers ----------------
__device__ __forceinline__ uint32_t smem_u32(const void* p){
  uint32_t a;
  asm("{ .reg .u64 t; cvta.to.shared.u64 t, %1; cvt.u32.u64 %0, t; }" : "=r"(a) : "l"(p));
  return a;
}
__device__ __forceinline__ void bsplit(float a, float b, uint32_t& hi, uint32_t& lo){
  __nv_bfloat16 ha = __float2bfloat16(a), hb = __float2bfloat16(b);
  float ra = a - __bfloat162float(ha);
  float rb = b - __bfloat162float(hb);
  __nv_bfloat16 la = __float2bfloat16(ra), lb = __float2bfloat16(rb);
  hi = ((uint32_t)__bfloat16_as_ushort(hb) << 16) | (uint32_t)__bfloat16_as_ushort(ha);
  lo = ((uint32_t)__bfloat16_as_ushort(lb) << 16) | (uint32_t)__bfloat16_as_ushort(la);
}
__device__ __forceinline__ void mma_bf16(float* c,
    uint32_t a0, uint32_t a1, uint32_t a2, uint32_t a3,
    uint32_t b0, uint32_t b1){
  asm volatile("mma.sync.aligned.m16n8k16.row.col.f32.bf16.bf16.f32 "
    "{%0,%1,%2,%3}, {%4,%5,%6,%7}, {%8,%9}, {%0,%1,%2,%3};"
    : "+f"(c[0]), "+f"(c[1]), "+f"(c[2]), "+f"(c[3])
    : "r"(a0), "r"(a1), "r"(a2), "r"(a3), "r"(b0), "r"(b1));
}
__device__ __forceinline__ void ldsm4(uint32_t* r, uint32_t addr){
  asm volatile("ldmatrix.sync.aligned.m8n8.x4.shared.b16 {%0,%1,%2,%3}, [%4];"
    : "=r"(r[0]), "=r"(r[1]), "=r"(r[2]), "=r"(r[3]) : "r"(addr));
}
#define CP_ASYNC16(dst, src) asm volatile("cp.async.cg.shared.global [%0], [%1], 16;" :: "r"(dst), "l"(src))
#define CP_COMMIT()  asm volatile("cp.async.commit_group;" ::: "memory")
#define CP_WAIT(n)   asm volatile("cp.async.wait_group %0;" :: "n"(n) : "memory")

// copy 128x64-word plane (row-major) to smem; 512 threads
__device__ __forceinline__ void cpb(uint32_t sb, int wbase, const uint32_t* __restrict__ gsrc){
  int tid = threadIdx.x;
  #pragma unroll
  for (int it = 0; it < 4; it++){
    int c = tid + it*512;
    int row = c >> 4, cw = (c & 15) * 4;
    CP_ASYNC16(sb + (uint32_t)(wbase + row*PITCH + cw)*4, gsrc + row*64 + cw);
  }
}

// core: acc[2][4][4] += A @ B^T; warp owns 32 rows x 32 cols; bf16 3-term split
__device__ __forceinline__ void mma_core(uint32_t a_hi, uint32_t a_lo,
                                         uint32_t b_hi, uint32_t b_lo,
                                         float acc[2][4][4]){
  #pragma unroll
  for (int s = 0; s < 8; s++){
    uint32_t k2b = s*32;
    uint32_t ah[2][4], al[2][4];
    ldsm4(ah[0], a_hi + k2b);
    ldsm4(ah[1], a_hi + 16*PITCH*4 + k2b);
    ldsm4(al[0], a_lo + k2b);
    ldsm4(al[1], a_lo + 16*PITCH*4 + k2b);
    uint32_t bh[2][4], bl[2][4];
    #pragma unroll
    for (int p = 0; p < 2; p++){
      ldsm4(bh[p], b_hi + (uint32_t)p*16*PITCH*4 + k2b);
      ldsm4(bl[p], b_lo + (uint32_t)p*16*PITCH*4 + k2b);
    }
    #pragma unroll
    for (int p = 0; p < 2; p++)
      #pragma unroll
      for (int e = 0; e < 2; e++){
        int nt = p*2 + e;
        uint32_t b0h = bh[p][e*2], b1h = bh[p][e*2+1];
        uint32_t b0l = bl[p][e*2], b1l = bl[p][e*2+1];
        #pragma unroll
        for (int mt = 0; mt < 2; mt++){
          mma_bf16(acc[mt][nt], ah[mt][0],ah[mt][1],ah[mt][2],ah[mt][3], b0h, b1h);
          mma_bf16(acc[mt][nt], ah[mt][0],ah[mt][1],ah[mt][2],ah[mt][3], b0l, b1l);
          mma_bf16(acc[mt][nt], al[mt][0],al[mt][1],al[mt][2],al[mt][3], b0h, b1h);
        }
      }
  }
}

// ---------------- hash helpers ----------------
__device__ __forceinline__ unsigned hmix(int k){
  unsigned x = (unsigned)k; x *= 2654435761u; x ^= x >> 15; return x & TMASK;
}
__device__ __forceinline__ void hinsert_count(int* keys, int* vals, int key){
  unsigned slot = hmix(key);
  while (true){
    int prev = atomicCAS(&keys[slot], -1, key);
    if (prev == -1 || prev == key){ atomicAdd(&vals[slot], 1); return; }
    slot = (slot + 1) & TMASK;
  }
}
__device__ __forceinline__ void hinsert_set(int* keys, int key){
  unsigned slot = hmix(key);
  while (true){
    int prev = atomicCAS(&keys[slot], -1, key);
    if (prev == -1 || prev == key) return;
    slot = (slot + 1) & TMASK;
  }
}
__device__ __forceinline__ int hcount(const int* __restrict__ keys, const int* __restrict__ vals, int key){
  unsigned slot = hmix(key);
  while (true){
    int k = keys[slot];
    if (k == key) return vals[slot];
    if (k == -1) return 0;
    slot = (slot + 1) & TMASK;
  }
}
__device__ __forceinline__ bool hmember(const int* __restrict__ keys, int key){
  unsigned slot = hmix(key);
  while (true){
    int k = keys[slot];
    if (k == key) return true;
    if (k == -1) return false;
    slot = (slot + 1) & TMASK;
  }
}

// ---------------- init / build / wsplit / scan / scatter ----------------
__global__ void k_init(){
  int i = blockIdx.x*blockDim.x + threadIdx.x;
  int stride = gridDim.x*blockDim.x;
  for (int j=i;j<(int)TS;j+=stride){
    g_ck_ui[j]=-1; g_ck_iu[j]=-1; g_rk_ui[j]=-1; g_rk_iu[j]=-1;
    g_cv_ui[j]=0;  g_cv_iu[j]=0;
  }
  for (int j=i;j<NN;j+=stride){ g_deg_u[j]=0; g_deg_i[j]=0; g_indeg_u[j]=0; g_indeg_i[j]=0; }
}

__global__ void k_build(const int* __restrict__ eui, const int* __restrict__ eiu){
  int i = blockIdx.x*blockDim.x + threadIdx.x;
  if (i < EE){
    int su = eui[i], du = eui[EE+i];
    hinsert_count(g_ck_ui, g_cv_ui, su*NN + du);
    hinsert_set  (g_rk_iu, du*NN + su);
    atomicAdd(&g_deg_u[su],1); atomicAdd(&g_deg_i[du],1); atomicAdd(&g_indeg_i[du],1);
  } else if (i < 2*EE){
    int j = i - EE;
    int si = eiu[j], di = eiu[EE+j];
    hinsert_count(g_ck_iu, g_cv_iu, si*NN + di);
    hinsert_set  (g_rk_ui, di*NN + si);
    atomicAdd(&g_deg_i[si],1); atomicAdd(&g_deg_u[di],1); atomicAdd(&g_indeg_u[di],1);
  }
}

__global__ void k_wsplit(const float* __restrict__ Wq, const float* __restrict__ Wk,
                         const float* __restrict__ Wv, const float* __restrict__ Wo){
  const float* Ws[4] = {Wq, Wk, Wv, Wo};
  int m = blockIdx.y;
  int i = blockIdx.x*256 + threadIdx.x;
  float2 v = *(const float2*)(Ws[m] + i*2);
  uint32_t hi, lo; bsplit(v.x, v.y, hi, lo);
  g_Whi[m][i] = hi; g_Wlo[m][i] = lo;
}

// coalesced smem-staged exclusive prefix sum.  2 CTAs (one per relation), 1024 thr.
__global__ void k_scan2(){
  extern __shared__ int ss[];          // [40960] values + [1024] thread bases
  int* basep = ss + 40960;
  __shared__ int wsum[32];
  __shared__ int woff[33];
  const int* indeg = blockIdx.x ? g_indeg_u : g_indeg_i;
  int* off = blockIdx.x ? g_off_u : g_off_i;
  int* cur = blockIdx.x ? g_cur_u : g_cur_i;
  int tid = threadIdx.x, lane = tid & 31, wid = tid >> 5;
  // coalesced load into smem
  #pragma unroll
  for (int it = 0; it < 40; it++){
    int i = it*1024 + tid;
    ss[i] = (i < NN) ? indeg[i] : 0;
  }
  __syncthreads();
  // per-thread serial exclusive scan in smem
  int s = 0, b = tid*40;
  #pragma unroll 8
  for (int j = 0; j < 40; j++){ int t = ss[b+j]; ss[b+j] = s; s += t; }
  // hierarchical scan of per-thread sums
  int inc = s;
  #pragma unroll
  for (int o=1;o<32;o<<=1){
    int t = __shfl_up_sync(0xffffffffu, inc, o);
    if (lane >= o) inc += t;
  }
  if (lane == 31) wsum[wid] = inc;
  __syncthreads();
  if (wid == 0){
    int vi = wsum[lane];
    #pragma unroll
    for (int o=1;o<32;o<<=1){
      int t = __shfl_up_sync(0xffffffffu, vi, o);
      if (lane >= o) vi += t;
    }
    woff[lane+1] = vi;
    if (lane == 0) woff[0] = 0;
  }
  __syncthreads();
  basep[tid] = woff[wid] + inc - s;
  __syncthreads();
  // coalesced write-out
  #pragma unroll
  for (int it = 0; it < 40; it++){
    int i = it*1024 + tid;
    if (i < NN){
      int v = ss[i] + basep[i/40];
      off[i] = v; cur[i] = v;
    }
  }
  if (tid == 0) off[NN] = woff[32];
}

__global__ void k_scatter(const int* __restrict__ eui, const int* __restrict__ eiu){
  int i = blockIdx.x*blockDim.x + threadIdx.x;
  if (i < EE){
    int s = eui[i], d = eui[EE+i];
    int pos = atomicAdd(&g_cur_i[d], 1);
    g_csr_ui[pos] = s;
  } else if (i < 2*EE){
    int j = i - EE;
    int s = eiu[j], d = eiu[EE+j];
    int pos = atomicAdd(&g_cur_u[d], 1);
    g_csr_iu[pos] = s;
  }
}

// ---------------- fused QKV GEMMs (512 threads, 4x4 warp grid) ----------------
__global__ __launch_bounds__(512,1) void k_qkv3(
    const float* __restrict__ Xu, const float* __restrict__ Xi,
    float* __restrict__ Qu, float* __restrict__ Ku, float* __restrict__ Vu,
    float* __restrict__ Qi, float* __restrict__ Ki, float* __restrict__ Vi,
    const float* __restrict__ bq, const float* __restrict__ bk, const float* __restrict__ bv){
  extern __shared__ uint32_t sm[];
  uint32_t sb = smem_u32(sm);
  int tid = threadIdx.x, lane = tid & 31, wid = tid >> 5;
  int mw = wid & 3, nw = wid >> 2, tg = lane >> 2, tq = lane & 3;
  int row0 = blockIdx.x * MT;
  const float* X = blockIdx.y ? Xi : Xu;
  float* Ys[3];
  if (blockIdx.y == 0){ Ys[0]=Qu; Ys[1]=Ku; Ys[2]=Vu; }
  else               { Ys[0]=Qi; Ys[1]=Ki; Ys[2]=Vi; }
  const float* bs[3] = {bq, bk, bv};

  #pragma unroll
  for (int it = 0; it < 16; it++){
    int idx = tid + it*512;
    int row = idx >> 6, j = idx & 63;
    int gr = row0 + row;
    float2 v = make_float2(0.f, 0.f);
    if (gr < NN) v = *(const float2*)(X + (size_t)gr*CC + j*2);
    uint32_t hi, lo; bsplit(v.x, v.y, hi, lo);
    sm[AHI + row*PITCH + j] = hi;
    sm[ALO + row*PITCH + j] = lo;
  }

  cpb(sb, B0HI, g_Whi[0]); cpb(sb, B0LO, g_Wlo[0]); CP_COMMIT();

  uint32_t a_toff = (uint32_t)(((mw*32 + (lane&15))*PITCH + (lane>>4)*4))*4;
  uint32_t b_toff = (uint32_t)(((nw*32 + (lane&7) + (lane>>4)*8)*PITCH + ((lane>>3)&1)*4))*4;
  uint32_t a_hi = sb + (uint32_t)AHI*4 + a_toff;
  uint32_t a_lo = sb + (uint32_t)ALO*4 + a_toff;

  #pragma unroll
  for (int m = 0; m < 3; m++){
    if (m < 2){
      int wb_hi = ((m+1)&1) ? B1HI : B0HI;
      int wb_lo = ((m+1)&1) ? B1LO : B0LO;
      cpb(sb, wb_hi, g_Whi[m+1]); cpb(sb, wb_lo, g_Wlo[m+1]); CP_COMMIT();
      CP_WAIT(1);
    } else {
      CP_WAIT(0);
    }
    __syncthreads();

    float acc[2][4][4];
    #pragma unroll
    for (int a=0;a<2;a++)
      #pragma unroll
      for (int b=0;b<4;b++)
        #pragma unroll
        for (int c=0;c<4;c++) acc[a][b][c]=0.f;

    uint32_t b_hi = sb + (uint32_t)((m&1) ? B1HI : B0HI)*4 + b_toff;
    uint32_t b_lo = sb + (uint32_t)((m&1) ? B1LO : B0LO)*4 + b_toff;
    mma_core(a_hi, a_lo, b_hi, b_lo, acc);

    const float* bias = bs[m];
    float* Y = Ys[m];
    #pragma unroll
    for (int mt = 0; mt < 2; mt++){
      int r = row0 + mw*32 + mt*16 + tg;
      #pragma unroll
      for (int nt = 0; nt < 4; nt++){
        int col = nw*32 + nt*8 + tq*2;
        float2 bb = *(const float2*)(bias + col);
        if (r < NN)
          *(float2*)(Y + (size_t)r*CC + col) = make_float2(acc[mt][nt][0]+bb.x, acc[mt][nt][1]+bb.y);
        if (r + 8 < NN)
          *(float2*)(Y + (size_t)(r+8)*CC + col) = make_float2(acc[mt][nt][2]+bb.x, acc[mt][nt][3]+bb.y);
      }
    }
    __syncthreads();
  }
}

// ---------------- CSR aggregation: warp per destination, both relations ----------------
__global__ __launch_bounds__(256) void k_agg2(
    const float* __restrict__ Qi, const float* __restrict__ Ku, const float* __restrict__ Vu,
    const float* __restrict__ Qu, const float* __restrict__ Ki, const float* __restrict__ Vi,
    const float* __restrict__ t_user, const float* __restrict__ t_item,
    const float* __restrict__ hb, const float* __restrict__ beta2,
    const float* __restrict__ tau_raw,
    const float* __restrict__ gamma2, const float* __restrict__ delta2){
  int r = blockIdx.y;
  int d = blockIdx.x*8 + (threadIdx.x>>5);
  if (d >= NN) return;
  int lane = threadIdx.x & 31;
  int h = lane >> 3;
  const int* off   = r ? g_off_u  : g_off_i;
  const int* csrc  = r ? g_csr_iu : g_csr_ui;
  const float* Q   = r ? Qu : Qi;
  const float* K   = r ? Ki : Ku;
  const float* V   = r ? Vi : Vu;
  const float* ts  = r ? t_item : t_user;
  const float* tdv = r ? t_user : t_item;
  const int* ckeys = r ? g_ck_iu : g_ck_ui;
  const int* cvals = r ? g_cv_iu : g_cv_ui;
  const int* rkeys = r ? g_rk_iu : g_rk_ui;
  float* agg       = r ? g_agg_u : g_agg_i;

  int beg = off[d], end = off[d+1];
  float4 q = __ldg((const float4*)(Q + (size_t)d*CC) + lane);
  float hbh = hb[r*HH+h], bh = beta2[r*HH+h], gh = gamma2[r*HH+h], dh = delta2[r*HH+h];
  float traw = tau_raw[r];
  float tau = (traw > 20.f) ? traw : log1pf(expf(traw));
  tau += 1e-6f;
  float td = tdv[d];
  float4 acc = make_float4(0.f,0.f,0.f,0.f);
  float z = 0.f;
  for (int base = beg; base < end; base += 32){
    int m = end - base; if (m > 32) m = 32;
    int s = 0; float tl = 0.f, lc = 0.f, rec = 0.f;
    if (lane < m){
      s = csrc[base + lane];
      float dt = fabsf(td - ts[s]) + 1e-6f;
      tl = -log1pf(dt / tau);
      int pid = s*NN + d;
      lc = log1pf((float)(hcount(ckeys, cvals, pid) - 1));
      rec = hmember(rkeys, pid) ? 1.f : 0.f;
    }
    for (int j = 0; j < m; j++){
      int sj    = __shfl_sync(0xffffffffu, s,   j);
      float tlj = __shfl_sync(0xffffffffu, tl,  j);
      float lcj = __shfl_sync(0xffffffffu, lc,  j);
      float rcj = __shfl_sync(0xffffffffu, rec, j);
      float4 kk = __ldg((const float4*)(K + (size_t)sj*CC) + lane);
      float4 vv = __ldg((const float4*)(V + (size_t)sj*CC) + lane);
      float p = q.x*kk.x + q.y*kk.y + q.z*kk.z + q.w*kk.w;
      p += __shfl_xor_sync(0xffffffffu, p, 1);
      p += __shfl_xor_sync(0xffffffffu, p, 2);
      p += __shfl_xor_sync(0xffffffffu, p, 4);
      float sc = p*0.17677669529663687f + hbh + tlj*bh + lcj*gh + rcj*dh;
      float w = expf(sc);
      z += w;
      acc.x += vv.x*w; acc.y += vv.y*w; acc.z += vv.z*w; acc.w += vv.w*w;
    }
  }
  float inv = (z > 0.f) ? (1.f/z) : 0.f;
  *(float4*)(agg + (size_t)d*CC + lane*4) =
      make_float4(acc.x*inv, acc.y*inv, acc.z*inv, acc.w*inv);
}

// ---------------- epilogue (512 threads): LN(agg@Wo^T + indeg*bo + deg + x) ----------------
__global__ __launch_bounds__(512,1) void k_out_mma(
    const float* __restrict__ aggu, const float* __restrict__ aggi,
    const float* __restrict__ bias,
    const int* __restrict__ indegu, const int* __restrict__ indegi,
    const int* __restrict__ degu, const int* __restrict__ degi,
    const float* __restrict__ xu, const float* __restrict__ xi,
    float* __restrict__ out){
  extern __shared__ uint32_t sm[];
  uint32_t sb = smem_u32(sm);
  int tid = threadIdx.x, lane = tid & 31, wid = tid >> 5;
  int mw = wid & 3, nw = wid >> 2, tg = lane >> 2, tq = lane & 3;
  int row0 = blockIdx.x * MT;
  const float* agg; const int* indeg; const int* deg; const float* xres; float* o;
  if (blockIdx.y == 0){ agg=aggu; indeg=indegu; deg=degu; xres=xu; o=out; }
  else { agg=aggi; indeg=indegi; deg=degi; xres=xi; o=out + (size_t)NN*CC; }

  cpb(sb, B0HI, g_Whi[3]); cpb(sb, B0LO, g_Wlo[3]); CP_COMMIT();

  #pragma unroll
  for (int it = 0; it < 16; it++){
    int idx = tid + it*512;
    int row = idx >> 6, j = idx & 63;
    int gr = row0 + row;
    float2 v = make_float2(0.f, 0.f);
    if (gr < NN) v = *(const float2*)(agg + (size_t)gr*CC + j*2);
    uint32_t hi, lo; bsplit(v.x, v.y, hi, lo);
    sm[AHI + row*PITCH + j] = hi;
    sm[ALO + row*PITCH + j] = lo;
  }
  CP_WAIT(0);
  __syncthreads();

  uint32_t a_toff = (uint32_t)(((mw*32 + (lane&15))*PITCH + (lane>>4)*4))*4;
  uint32_t b_toff = (uint32_t)(((nw*32 + (lane&7) + (lane>>4)*8)*PITCH + ((lane>>3)&1)*4))*4;

  float acc[2][4][4];
  #pragma unroll
  for (int a=0;a<2;a++)
    #pragma unroll
    for (int b=0;b<4;b++)
      #pragma unroll
      for (int c=0;c<4;c++) acc[a][b][c]=0.f;

  mma_core(sb + (uint32_t)AHI*4 + a_toff, sb + (uint32_t)ALO*4 + a_toff,
           sb + (uint32_t)B0HI*4 + b_toff, sb + (uint32_t)B0LO*4 + b_toff, acc);

  float* reds = (float*)(sm + RED0);          // 512 floats
  float* redq = (float*)(sm + RED0 + 512);    // 512 floats

  float2 bb[4];
  #pragma unroll
  for (int nt = 0; nt < 4; nt++) bb[nt] = *(const float2*)(bias + nw*32 + nt*8 + tq*2);

  #pragma unroll
  for (int mt = 0; mt < 2; mt++){
    #pragma unroll
    for (int h = 0; h < 2; h++){
      int lr = mw*32 + mt*16 + tg + h*8;
      int grow = row0 + lr;
      float dg = 0.f, idg = 0.f;
      if (grow < NN){ dg = (float)deg[grow]; idg = (float)indeg[grow]; }
      float s = 0.f;
      #pragma unroll
      for (int nt = 0; nt < 4; nt++){
        int col = nw*32 + nt*8 + tq*2;
        float2 xr = make_float2(0.f, 0.f);
        if (grow < NN) xr = *(const float2*)(xres + (size_t)grow*CC + col);
        float v0 = acc[mt][nt][h*2+0] + bb[nt].x*idg + dg + xr.x;
        float v1 = acc[mt][nt][h*2+1] + bb[nt].y*idg + dg + xr.y;
        acc[mt][nt][h*2+0] = v0;
        acc[mt][nt][h*2+1] = v1;
        s += v0 + v1;
      }
      s += __shfl_xor_sync(0xffffffffu, s, 1);
      s += __shfl_xor_sync(0xffffffffu, s, 2);
      if (tq == 0) reds[lr*4 + nw] = s;
    }
  }
  __syncthreads();

  float mu[2][2];
  #pragma unroll
  for (int mt = 0; mt < 2; mt++)
    #pragma unroll
    for (int h = 0; h < 2; h++){
      int lr = mw*32 + mt*16 + tg + h*8;
      mu[mt][h] = (reds[lr*4] + reds[lr*4+1] + reds[lr*4+2] + reds[lr*4+3]) * (1.f/128.f);
    }

  #pragma unroll
  for (int mt = 0; mt < 2; mt++){
    #pragma unroll
    for (int h = 0; h < 2; h++){
      int lr = mw*32 + mt*16 + tg + h*8;
      float q = 0.f;
      #pragma unroll
      for (int nt = 0; nt < 4; nt++){
        float d0 = acc[mt][nt][h*2+0] - mu[mt][h];
        float d1 = acc[mt][nt][h*2+1] - mu[mt][h];
        q += d0*d0 + d1*d1;
      }
      q += __shfl_xor_sync(0xffffffffu, q, 1);
      q += __shfl_xor_sync(0xffffffffu, q, 2);
      if (tq == 0) redq[lr*4 + nw] = q;
    }
  }
  __syncthreads();

  #pragma unroll
  for (int mt = 0; mt < 2; mt++){
    #pragma unroll
    for (int h = 0; h < 2; h++){
      int lr = mw*32 + mt*16 + tg + h*8;
      int grow = row0 + lr;
      if (grow >= NN) continue;
      float var = (redq[lr*4] + redq[lr*4+1] + redq[lr*4+2] + redq[lr*4+3]) * (1.f/128.f);
      float rs = rsqrtf(var + 1e-5f);
      float m = mu[mt][h];
      #pragma unroll
      for (int nt = 0; nt < 4; nt++){
        int col = nw*32 + nt*8 + tq*2;
        *(float2*)(o + (size_t)grow*CC + col) =
          make_float2((acc[mt][nt][h*2+0]-m)*rs, (acc[mt][nt][h*2+1]-m)*rs);
      }
    }
  }
}

// ---------------- launch ----------------
extern "C" void kernel_launch(void* const* d_in, const int* in_sizes, int n_in,
                              void* d_out, int out_size){
  const float* x_user=(const float*)d_in[0];
  const float* x_item=(const float*)d_in[1];
  const float* t_user=(const float*)d_in[2];
  const float* t_item=(const float*)d_in[3];
  const int*   eui  =(const int*)  d_in[4];
  const int*   eiu  =(const int*)  d_in[5];
  const float* Wq=(const float*)d_in[6];  const float* bq=(const float*)d_in[7];
  const float* Wk=(const float*)d_in[8];  const float* bk=(const float*)d_in[9];
  const float* Wv=(const float*)d_in[10]; const float* bv=(const float*)d_in[11];
  const float* Wo=(const float*)d_in[12]; const float* bo=(const float*)d_in[13];
  const float* hb=(const float*)d_in[14];
  const float* tb=(const float*)d_in[15];
  const float* traw=(const float*)d_in[16];
  const float* gm=(const float*)d_in[17];
  const float* dr=(const float*)d_in[18];
  float* out=(float*)d_out;

  float *Qu,*Ku,*Vu,*Qi,*Ki,*Vi,*aggu,*aggi;
  int *degu,*degi,*idgu,*idgi;
  cudaGetSymbolAddress((void**)&Qu, g_Qu);
  cudaGetSymbolAddress((void**)&Ku, g_Ku);
  cudaGetSymbolAddress((void**)&Vu, g_Vu);
  cudaGetSymbolAddress((void**)&Qi, g_Qi);
  cudaGetSymbolAddress((void**)&Ki, g_Ki);
  cudaGetSymbolAddress((void**)&Vi, g_Vi);
  cudaGetSymbolAddress((void**)&aggu, g_agg_u);
  cudaGetSymbolAddress((void**)&aggi, g_agg_i);
  cudaGetSymbolAddress((void**)&degu, g_deg_u);
  cudaGetSymbolAddress((void**)&degi, g_deg_i);
  cudaGetSymbolAddress((void**)&idgu, g_indeg_u);
  cudaGetSymbolAddress((void**)&idgi, g_indeg_i);

  cudaFuncSetAttribute(k_qkv3,   cudaFuncAttributeMaxDynamicSharedMemorySize, QKV_SMEMB);
  cudaFuncSetAttribute(k_out_mma,cudaFuncAttributeMaxDynamicSharedMemorySize, OUT_SMEMB);
  cudaFuncSetAttribute(k_scan2,  cudaFuncAttributeMaxDynamicSharedMemorySize, SCAN_SMEMB);

  // Fork a second stream inside graph capture: chain A (edge preprocessing)
  // overlaps with chain B (weight split + QKV GEMMs). Host objects only —
  // no device memory. kernel_launch runs twice total, leak is negligible.
  cudaStream_t s2;
  cudaStreamCreateWithFlags(&s2, cudaStreamNonBlocking);
  cudaEvent_t eFork, eJoin;
  cudaEventCreateWithFlags(&eFork, cudaEventDisableTiming);
  cudaEventCreateWithFlags(&eJoin, cudaEventDisableTiming);

  cudaEventRecord(eFork, 0);
  cudaStreamWaitEvent(s2, eFork, 0);

  // chain A on s2: hash tables + degrees + CSR
  k_init<<<1024,256,0,s2>>>();
  k_build<<<(2*EE+255)/256,256,0,s2>>>(eui, eiu);
  k_scan2<<<2,1024,SCAN_SMEMB,s2>>>();
  k_scatter<<<(2*EE+255)/256,256,0,s2>>>(eui, eiu);
  cudaEventRecord(eJoin, s2);

  // chain B on capture stream: weight planes + QKV projections
  k_wsplit<<<dim3(32,4),256>>>(Wq, Wk, Wv, Wo);
  k_qkv3<<<dim3(NBLK,2),512,QKV_SMEMB>>>(x_user, x_item, Qu,Ku,Vu, Qi,Ki,Vi, bq,bk,bv);

  // join: aggregation needs both chains
  cudaStreamWaitEvent(0, eJoin, 0);

  // both relations in one launch (r = blockIdx.y: 0 = user->item, 1 = item->user)
  k_agg2<<<dim3((NN+7)/8,2),256>>>(Qi, Ku, Vu, Qu, Ki, Vi, t_user, t_item,
                                   hb, tb, traw, gm, dr);

  k_out_mma<<<dim3(NBLK,2),512,OUT_SMEMB>>>(aggu, aggi, bo,
                                            idgu, idgi, degu, degi,
                                            x_user, x_item, out);
}

// round 10
// speedup vs baseline: 2.3629x; 1.0614x over previous
#include <cuda_runtime.h>
#include <cuda_bf16.h>
#include <math.h>
#include <stdint.h>

#define NN 40000
#define CC 128
#define HH 4
#define EE 200000
#define TS (1u<<19)
#define TMASK (TS-1u)

#define MT 128
#define NBLK ((NN + MT - 1) / MT)        // 313
#define PITCH 68
#define PLANE (128*PITCH)                // 8704 words
#define AHI 0
#define ALO PLANE
#define B0HI (2*PLANE)
#define B0LO (3*PLANE)
#define B1HI (4*PLANE)
#define B1LO (5*PLANE)
#define RED0 (4*PLANE)                   // k_out only (reuses B1 space)
#define QKV_SMEMB (6*PLANE*4)            // 208896 B
#define OUT_SMEMB ((4*PLANE+1024)*4)
#define SCAN_SMEMB ((40960+1024)*4)      // 167936 B

// ---------------- scratch (device globals) ----------------
__device__ float g_Qu[NN*CC], g_Ku[NN*CC], g_Vu[NN*CC];
__device__ float g_Qi[NN*CC], g_Ki[NN*CC], g_Vi[NN*CC];
__device__ float g_agg_u[NN*CC], g_agg_i[NN*CC];
__device__ uint32_t g_Whi[4][CC*CC/2], g_Wlo[4][CC*CC/2];   // q,k,v,o
__device__ int g_ck_ui[TS], g_cv_ui[TS];
__device__ int g_ck_iu[TS], g_cv_iu[TS];
__device__ int g_rk_ui[TS], g_rk_iu[TS];
__device__ int g_deg_u[NN], g_deg_i[NN], g_indeg_u[NN], g_indeg_i[NN];
__device__ int g_off_i[NN+1], g_off_u[NN+1];
__device__ int g_cur_i[NN], g_cur_u[NN];
__device__ int g_csr_ui[EE], g_csr_iu[EE];   // src ids grouped by dst

// ---------------- helpers ----------------
__device__ __forceinline__ uint32_t smem_u32(const void* p){
  uint32_t a;
  asm("{ .reg .u64 t; cvta.to.shared.u64 t, %1; cvt.u32.u64 %0, t; }" : "=r"(a) : "l"(p));
  return a;
}
__device__ __forceinline__ void bsplit(float a, float b, uint32_t& hi, uint32_t& lo){
  __nv_bfloat16 ha = __float2bfloat16(a), hb = __float2bfloat16(b);
  float ra = a - __bfloat162float(ha);
  float rb = b - __bfloat162float(hb);
  __nv_bfloat16 la = __float2bfloat16(ra), lb = __float2bfloat16(rb);
  hi = ((uint32_t)__bfloat16_as_ushort(hb) << 16) | (uint32_t)__bfloat16_as_ushort(ha);
  lo = ((uint32_t)__bfloat16_as_ushort(lb) << 16) | (uint32_t)__bfloat16_as_ushort(la);
}
__device__ __forceinline__ void mma_bf16(float* c,
    uint32_t a0, uint32_t a1, uint32_t a2, uint32_t a3,
    uint32_t b0, uint32_t b1){
  asm volatile("mma.sync.aligned.m16n8k16.row.col.f32.bf16.bf16.f32 "
    "{%0,%1,%2,%3}, {%4,%5,%6,%7}, {%8,%9}, {%0,%1,%2,%3};"
    : "+f"(c[0]), "+f"(c[1]), "+f"(c[2]), "+f"(c[3])
    : "r"(a0), "r"(a1), "r"(a2), "r"(a3), "r"(b0), "r"(b1));
}
__device__ __forceinline__ void ldsm4(uint32_t* r, uint32_t addr){
  asm volatile("ldmatrix.sync.aligned.m8n8.x4.shared.b16 {%0,%1,%2,%3}, [%4];"
    : "=r"(r[0]), "=r"(r[1]), "=r"(r[2]), "=r"(r[3]) : "r"(addr));
}
#define CP_ASYNC16(dst, src) asm volatile("cp.async.cg.shared.global [%0], [%1], 16;" :: "r"(dst), "l"(src))
#define CP_COMMIT()  asm volatile("cp.async.commit_group;" ::: "memory")
#define CP_WAIT(n)   asm volatile("cp.async.wait_group %0;" :: "n"(n) : "memory")

// copy 128x64-word plane (row-major) to smem; 512 threads
__device__ __forceinline__ void cpb(uint32_t sb, int wbase, const uint32_t* __restrict__ gsrc){
  int tid = threadIdx.x;
  #pragma unroll
  for (int it = 0; it < 4; it++){
    int c = tid + it*512;
    int row = c >> 4, cw = (c & 15) * 4;
    CP_ASYNC16(sb + (uint32_t)(wbase + row*PITCH + cw)*4, gsrc + row*64 + cw);
  }
}

// core: acc[2][4][4] += A @ B^T; warp owns 32 rows x 32 cols; bf16 3-term split
__device__ __forceinline__ void mma_core(uint32_t a_hi, uint32_t a_lo,
                                         uint32_t b_hi, uint32_t b_lo,
                                         float acc[2][4][4]){
  #pragma unroll
  for (int s = 0; s < 8; s++){
    uint32_t k2b = s*32;
    uint32_t ah[2][4], al[2][4];
    ldsm4(ah[0], a_hi + k2b);
    ldsm4(ah[1], a_hi + 16*PITCH*4 + k2b);
    ldsm4(al[0], a_lo + k2b);
    ldsm4(al[1], a_lo + 16*PITCH*4 + k2b);
    uint32_t bh[2][4], bl[2][4];
    #pragma unroll
    for (int p = 0; p < 2; p++){
      ldsm4(bh[p], b_hi + (uint32_t)p*16*PITCH*4 + k2b);
      ldsm4(bl[p], b_lo + (uint32_t)p*16*PITCH*4 + k2b);
    }
    #pragma unroll
    for (int p = 0; p < 2; p++)
      #pragma unroll
      for (int e = 0; e < 2; e++){
        int nt = p*2 + e;
        uint32_t b0h = bh[p][e*2], b1h = bh[p][e*2+1];
        uint32_t b0l = bl[p][e*2], b1l = bl[p][e*2+1];
        #pragma unroll
        for (int mt = 0; mt < 2; mt++){
          mma_bf16(acc[mt][nt], ah[mt][0],ah[mt][1],ah[mt][2],ah[mt][3], b0h, b1h);
          mma_bf16(acc[mt][nt], ah[mt][0],ah[mt][1],ah[mt][2],ah[mt][3], b0l, b1l);
          mma_bf16(acc[mt][nt], al[mt][0],al[mt][1],al[mt][2],al[mt][3], b0h, b1h);
        }
      }
  }
}

// ---------------- hash helpers ----------------
__device__ __forceinline__ unsigned hmix(int k){
  unsigned x = (unsigned)k; x *= 2654435761u; x ^= x >> 15; return x & TMASK;
}
__device__ __forceinline__ void hinsert_count(int* keys, int* vals, int key){
  unsigned slot = hmix(key);
  while (true){
    int prev = atomicCAS(&keys[slot], -1, key);
    if (prev == -1 || prev == key){ atomicAdd(&vals[slot], 1); return; }
    slot = (slot + 1) & TMASK;
  }
}
__device__ __forceinline__ void hinsert_set(int* keys, int key){
  unsigned slot = hmix(key);
  while (true){
    int prev = atomicCAS(&keys[slot], -1, key);
    if (prev == -1 || prev == key) return;
    slot = (slot + 1) & TMASK;
  }
}
__device__ __forceinline__ int hcount(const int* __restrict__ keys, const int* __restrict__ vals, int key){
  unsigned slot = hmix(key);
  while (true){
    int k = keys[slot];
    if (k == key) return vals[slot];
    if (k == -1) return 0;
    slot = (slot + 1) & TMASK;
  }
}
__device__ __forceinline__ bool hmember(const int* __restrict__ keys, int key){
  unsigned slot = hmix(key);
  while (true){
    int k = keys[slot];
    if (k == key) return true;
    if (k == -1) return false;
    slot = (slot + 1) & TMASK;
  }
}

// ---------------- init / build / wsplit / scan / scatter ----------------
__global__ void k_init(){
  int i = blockIdx.x*blockDim.x + threadIdx.x;
  int stride = gridDim.x*blockDim.x;
  for (int j=i;j<(int)TS;j+=stride){
    g_ck_ui[j]=-1; g_ck_iu[j]=-1; g_rk_ui[j]=-1; g_rk_iu[j]=-1;
    g_cv_ui[j]=0;  g_cv_iu[j]=0;
  }
  for (int j=i;j<NN;j+=stride){ g_deg_u[j]=0; g_deg_i[j]=0; g_indeg_u[j]=0; g_indeg_i[j]=0; }
}

__global__ void k_build(const int* __restrict__ eui, const int* __restrict__ eiu){
  int i = blockIdx.x*blockDim.x + threadIdx.x;
  if (i < EE){
    int su = eui[i], du = eui[EE+i];
    hinsert_count(g_ck_ui, g_cv_ui, su*NN + du);
    hinsert_set  (g_rk_iu, du*NN + su);
    atomicAdd(&g_deg_u[su],1); atomicAdd(&g_deg_i[du],1); atomicAdd(&g_indeg_i[du],1);
  } else if (i < 2*EE){
    int j = i - EE;
    int si = eiu[j], di = eiu[EE+j];
    hinsert_count(g_ck_iu, g_cv_iu, si*NN + di);
    hinsert_set  (g_rk_ui, di*NN + si);
    atomicAdd(&g_deg_i[si],1); atomicAdd(&g_deg_u[di],1); atomicAdd(&g_indeg_u[di],1);
  }
}

__global__ void k_wsplit(const float* __restrict__ Wq, const float* __restrict__ Wk,
                         const float* __restrict__ Wv, const float* __restrict__ Wo){
  const float* Ws[4] = {Wq, Wk, Wv, Wo};
  int m = blockIdx.y;
  int i = blockIdx.x*256 + threadIdx.x;
  float2 v = *(const float2*)(Ws[m] + i*2);
  uint32_t hi, lo; bsplit(v.x, v.y, hi, lo);
  g_Whi[m][i] = hi; g_Wlo[m][i] = lo;
}

// coalesced smem-staged exclusive prefix sum.  2 CTAs (one per relation), 1024 thr.
__global__ void k_scan2(){
  extern __shared__ int ss[];          // [40960] values + [1024] thread bases
  int* basep = ss + 40960;
  __shared__ int wsum[32];
  __shared__ int woff[33];
  const int* indeg = blockIdx.x ? g_indeg_u : g_indeg_i;
  int* off = blockIdx.x ? g_off_u : g_off_i;
  int* cur = blockIdx.x ? g_cur_u : g_cur_i;
  int tid = threadIdx.x, lane = tid & 31, wid = tid >> 5;
  // coalesced load into smem
  #pragma unroll
  for (int it = 0; it < 40; it++){
    int i = it*1024 + tid;
    ss[i] = (i < NN) ? indeg[i] : 0;
  }
  __syncthreads();
  // per-thread serial exclusive scan in smem
  int s = 0, b = tid*40;
  #pragma unroll 8
  for (int j = 0; j < 40; j++){ int t = ss[b+j]; ss[b+j] = s; s += t; }
  // hierarchical scan of per-thread sums
  int inc = s;
  #pragma unroll
  for (int o=1;o<32;o<<=1){
    int t = __shfl_up_sync(0xffffffffu, inc, o);
    if (lane >= o) inc += t;
  }
  if (lane == 31) wsum[wid] = inc;
  __syncthreads();
  if (wid == 0){
    int vi = wsum[lane];
    #pragma unroll
    for (int o=1;o<32;o<<=1){
      int t = __shfl_up_sync(0xffffffffu, vi, o);
      if (lane >= o) vi += t;
    }
    woff[lane+1] = vi;
    if (lane == 0) woff[0] = 0;
  }
  __syncthreads();
  basep[tid] = woff[wid] + inc - s;
  __syncthreads();
  // coalesced write-out
  #pragma unroll
  for (int it = 0; it < 40; it++){
    int i = it*1024 + tid;
    if (i < NN){
      int v = ss[i] + basep[i/40];
      off[i] = v; cur[i] = v;
    }
  }
  if (tid == 0) off[NN] = woff[32];
}

__global__ void k_scatter(const int* __restrict__ eui, const int* __restrict__ eiu){
  int i = blockIdx.x*blockDim.x + threadIdx.x;
  if (i < EE){
    int s = eui[i], d = eui[EE+i];
    int pos = atomicAdd(&g_cur_i[d], 1);
    g_csr_ui[pos] = s;
  } else if (i < 2*EE){
    int j = i - EE;
    int s = eiu[j], d = eiu[EE+j];
    int pos = atomicAdd(&g_cur_u[d], 1);
    g_csr_iu[pos] = s;
  }
}

// ---------------- fused QKV GEMMs (512 threads, 4x4 warp grid) ----------------
__global__ __launch_bounds__(512,1) void k_qkv3(
    const float* __restrict__ Xu, const float* __restrict__ Xi,
    float* __restrict__ Qu, float* __restrict__ Ku, float* __restrict__ Vu,
    float* __restrict__ Qi, float* __restrict__ Ki, float* __restrict__ Vi,
    const float* __restrict__ bq, const float* __restrict__ bk, const float* __restrict__ bv){
  extern __shared__ uint32_t sm[];
  uint32_t sb = smem_u32(sm);
  int tid = threadIdx.x, lane = tid & 31, wid = tid >> 5;
  int mw = wid & 3, nw = wid >> 2, tg = lane >> 2, tq = lane & 3;
  int row0 = blockIdx.x * MT;
  const float* X = blockIdx.y ? Xi : Xu;
  float* Ys[3];
  if (blockIdx.y == 0){ Ys[0]=Qu; Ys[1]=Ku; Ys[2]=Vu; }
  else               { Ys[0]=Qi; Ys[1]=Ki; Ys[2]=Vi; }
  const float* bs[3] = {bq, bk, bv};

  // B0 prefetch FIRST — overlap global fetch with bsplit-heavy A staging
  cpb(sb, B0HI, g_Whi[0]); cpb(sb, B0LO, g_Wlo[0]); CP_COMMIT();

  #pragma unroll
  for (int it = 0; it < 16; it++){
    int idx = tid + it*512;
    int row = idx >> 6, j = idx & 63;
    int gr = row0 + row;
    float2 v = make_float2(0.f, 0.f);
    if (gr < NN) v = *(const float2*)(X + (size_t)gr*CC + j*2);
    uint32_t hi, lo; bsplit(v.x, v.y, hi, lo);
    sm[AHI + row*PITCH + j] = hi;
    sm[ALO + row*PITCH + j] = lo;
  }

  uint32_t a_toff = (uint32_t)(((mw*32 + (lane&15))*PITCH + (lane>>4)*4))*4;
  uint32_t b_toff = (uint32_t)(((nw*32 + (lane&7) + (lane>>4)*8)*PITCH + ((lane>>3)&1)*4))*4;
  uint32_t a_hi = sb + (uint32_t)AHI*4 + a_toff;
  uint32_t a_lo = sb + (uint32_t)ALO*4 + a_toff;

  #pragma unroll
  for (int m = 0; m < 3; m++){
    if (m < 2){
      int wb_hi = ((m+1)&1) ? B1HI : B0HI;
      int wb_lo = ((m+1)&1) ? B1LO : B0LO;
      cpb(sb, wb_hi, g_Whi[m+1]); cpb(sb, wb_lo, g_Wlo[m+1]); CP_COMMIT();
      CP_WAIT(1);
    } else {
      CP_WAIT(0);
    }
    __syncthreads();

    float acc[2][4][4];
    #pragma unroll
    for (int a=0;a<2;a++)
      #pragma unroll
      for (int b=0;b<4;b++)
        #pragma unroll
        for (int c=0;c<4;c++) acc[a][b][c]=0.f;

    uint32_t b_hi = sb + (uint32_t)((m&1) ? B1HI : B0HI)*4 + b_toff;
    uint32_t b_lo = sb + (uint32_t)((m&1) ? B1LO : B0LO)*4 + b_toff;
    mma_core(a_hi, a_lo, b_hi, b_lo, acc);

    const float* bias = bs[m];
    float* Y = Ys[m];
    #pragma unroll
    for (int mt = 0; mt < 2; mt++){
      int r = row0 + mw*32 + mt*16 + tg;
      #pragma unroll
      for (int nt = 0; nt < 4; nt++){
        int col = nw*32 + nt*8 + tq*2;
        float2 bb = *(const float2*)(bias + col);
        if (r < NN)
          *(float2*)(Y + (size_t)r*CC + col) = make_float2(acc[mt][nt][0]+bb.x, acc[mt][nt][1]+bb.y);
        if (r + 8 < NN)
          *(float2*)(Y + (size_t)(r+8)*CC + col) = make_float2(acc[mt][nt][2]+bb.x, acc[mt][nt][3]+bb.y);
      }
    }
    __syncthreads();
  }
}

// ---------------- CSR aggregation: warp per destination, 4-edge MLP batches ----------------
__global__ __launch_bounds__(256) void k_agg2(
    const float* __restrict__ Qi, const float* __restrict__ Ku, const float* __restrict__ Vu,
    const float* __restrict__ Qu, const float* __restrict__ Ki, const float* __restrict__ Vi,
    const float* __restrict__ t_user, const float* __restrict__ t_item,
    const float* __restrict__ hb, const float* __restrict__ beta2,
    const float* __restrict__ tau_raw,
    const float* __restrict__ gamma2, const float* __restrict__ delta2){
  int r = blockIdx.y;
  int d = blockIdx.x*8 + (threadIdx.x>>5);
  if (d >= NN) return;
  int lane = threadIdx.x & 31;
  int h = lane >> 3;
  const int* off   = r ? g_off_u  : g_off_i;
  const int* csrc  = r ? g_csr_iu : g_csr_ui;
  const float* Q   = r ? Qu : Qi;
  const float* K   = r ? Ki : Ku;
  const float* V   = r ? Vi : Vu;
  const float* ts  = r ? t_item : t_user;
  const float* tdv = r ? t_user : t_item;
  const int* ckeys = r ? g_ck_iu : g_ck_ui;
  const int* cvals = r ? g_cv_iu : g_cv_ui;
  const int* rkeys = r ? g_rk_iu : g_rk_ui;
  float* agg       = r ? g_agg_u : g_agg_i;

  int beg = off[d], end = off[d+1];
  float4 q = __ldg((const float4*)(Q + (size_t)d*CC) + lane);
  float hbh = hb[r*HH+h], bh = beta2[r*HH+h], gh = gamma2[r*HH+h], dh = delta2[r*HH+h];
  float traw = tau_raw[r];
  float tau = (traw > 20.f) ? traw : log1pf(expf(traw));
  tau += 1e-6f;
  float td = tdv[d];
  float4 acc = make_float4(0.f,0.f,0.f,0.f);
  float z = 0.f;
  for (int base = beg; base < end; base += 32){
    int m = end - base; if (m > 32) m = 32;
    int s = 0; float tl = 0.f, lc = 0.f, rec = 0.f;
    if (lane < m){
      s = csrc[base + lane];
      float dt = fabsf(td - ts[s]) + 1e-6f;
      tl = -log1pf(dt / tau);
      int pid = s*NN + d;
      lc = log1pf((float)(hcount(ckeys, cvals, pid) - 1));
      rec = hmember(rkeys, pid) ? 1.f : 0.f;
    }
    int j = 0;
    // 4-edge batches: issue 8 independent loads before any compute (MLP=8)
    for (; j + 4 <= m; j += 4){
      int   s0  = __shfl_sync(0xffffffffu, s,   j+0);
      int   s1  = __shfl_sync(0xffffffffu, s,   j+1);
      int   s2  = __shfl_sync(0xffffffffu, s,   j+2);
      int   s3  = __shfl_sync(0xffffffffu, s,   j+3);
      float4 kk0 = __ldg((const float4*)(K + (size_t)s0*CC) + lane);
      float4 kk1 = __ldg((const float4*)(K + (size_t)s1*CC) + lane);
      float4 kk2 = __ldg((const float4*)(K + (size_t)s2*CC) + lane);
      float4 kk3 = __ldg((const float4*)(K + (size_t)s3*CC) + lane);
      float4 vv0 = __ldg((const float4*)(V + (size_t)s0*CC) + lane);
      float4 vv1 = __ldg((const float4*)(V + (size_t)s1*CC) + lane);
      float4 vv2 = __ldg((const float4*)(V + (size_t)s2*CC) + lane);
      float4 vv3 = __ldg((const float4*)(V + (size_t)s3*CC) + lane);
      float p0 = q.x*kk0.x + q.y*kk0.y + q.z*kk0.z + q.w*kk0.w;
      float p1 = q.x*kk1.x + q.y*kk1.y + q.z*kk1.z + q.w*kk1.w;
      float p2 = q.x*kk2.x + q.y*kk2.y + q.z*kk2.z + q.w*kk2.w;
      float p3 = q.x*kk3.x + q.y*kk3.y + q.z*kk3.z + q.w*kk3.w;
      #pragma unroll
      for (int o = 1; o <= 4; o <<= 1){
        p0 += __shfl_xor_sync(0xffffffffu, p0, o);
        p1 += __shfl_xor_sync(0xffffffffu, p1, o);
        p2 += __shfl_xor_sync(0xffffffffu, p2, o);
        p3 += __shfl_xor_sync(0xffffffffu, p3, o);
      }
      float e0 = p0*0.17677669529663687f + hbh
               + __shfl_sync(0xffffffffu, tl, j+0)*bh
               + __shfl_sync(0xffffffffu, lc, j+0)*gh
               + __shfl_sync(0xffffffffu, rec,j+0)*dh;
      float e1 = p1*0.17677669529663687f + hbh
               + __shfl_sync(0xffffffffu, tl, j+1)*bh
               + __shfl_sync(0xffffffffu, lc, j+1)*gh
               + __shfl_sync(0xffffffffu, rec,j+1)*dh;
      float e2 = p2*0.17677669529663687f + hbh
               + __shfl_sync(0xffffffffu, tl, j+2)*bh
               + __shfl_sync(0xffffffffu, lc, j+2)*gh
               + __shfl_sync(0xffffffffu, rec,j+2)*dh;
      float e3 = p3*0.17677669529663687f + hbh
               + __shfl_sync(0xffffffffu, tl, j+3)*bh
               + __shfl_sync(0xffffffffu, lc, j+3)*gh
               + __shfl_sync(0xffffffffu, rec,j+3)*dh;
      float w0 = expf(e0), w1 = expf(e1), w2 = expf(e2), w3 = expf(e3);
      z += (w0 + w1) + (w2 + w3);
      acc.x += vv0.x*w0 + vv1.x*w1 + vv2.x*w2 + vv3.x*w3;
      acc.y += vv0.y*w0 + vv1.y*w1 + vv2.y*w2 + vv3.y*w3;
      acc.z += vv0.z*w0 + vv1.z*w1 + vv2.z*w2 + vv3.z*w3;
      acc.w += vv0.w*w0 + vv1.w*w1 + vv2.w*w2 + vv3.w*w3;
    }
    for (; j < m; j++){
      int sj    = __shfl_sync(0xffffffffu, s,   j);
      float tlj = __shfl_sync(0xffffffffu, tl,  j);
      float lcj = __shfl_sync(0xffffffffu, lc,  j);
      float rcj = __shfl_sync(0xffffffffu, rec, j);
      float4 kk = __ldg((const float4*)(K + (size_t)sj*CC) + lane);
      float4 vv = __ldg((const float4*)(V + (size_t)sj*CC) + lane);
      float p = q.x*kk.x + q.y*kk.y + q.z*kk.z + q.w*kk.w;
      p += __shfl_xor_sync(0xffffffffu, p, 1);
      p += __shfl_xor_sync(0xffffffffu, p, 2);
      p += __shfl_xor_sync(0xffffffffu, p, 4);
      float sc = p*0.17677669529663687f + hbh + tlj*bh + lcj*gh + rcj*dh;
      float w = expf(sc);
      z += w;
      acc.x += vv.x*w; acc.y += vv.y*w; acc.z += vv.z*w; acc.w += vv.w*w;
    }
  }
  float inv = (z > 0.f) ? (1.f/z) : 0.f;
  *(float4*)(agg + (size_t)d*CC + lane*4) =
      make_float4(acc.x*inv, acc.y*inv, acc.z*inv, acc.w*inv);
}

// ---------------- epilogue (512 threads): LN(agg@Wo^T + indeg*bo + deg + x) ----------------
__global__ __launch_bounds__(512,1) void k_out_mma(
    const float* __restrict__ aggu, const float* __restrict__ aggi,
    const float* __restrict__ bias,
    const int* __restrict__ indegu, const int* __restrict__ indegi,
    const int* __restrict__ degu, const int* __restrict__ degi,
    const float* __restrict__ xu, const float* __restrict__ xi,
    float* __restrict__ out){
  extern __shared__ uint32_t sm[];
  uint32_t sb = smem_u32(sm);
  int tid = threadIdx.x, lane = tid & 31, wid = tid >> 5;
  int mw = wid & 3, nw = wid >> 2, tg = lane >> 2, tq = lane & 3;
  int row0 = blockIdx.x * MT;
  const float* agg; const int* indeg; const int* deg; const float* xres; float* o;
  if (blockIdx.y == 0){ agg=aggu; indeg=indegu; deg=degu; xres=xu; o=out; }
  else { agg=aggi; indeg=indegi; deg=degi; xres=xi; o=out + (size_t)NN*CC; }

  cpb(sb, B0HI, g_Whi[3]); cpb(sb, B0LO, g_Wlo[3]); CP_COMMIT();

  #pragma unroll
  for (int it = 0; it < 16; it++){
    int idx = tid + it*512;
    int row = idx >> 6, j = idx & 63;
    int gr = row0 + row;
    float2 v = make_float2(0.f, 0.f);
    if (gr < NN) v = *(const float2*)(agg + (size_t)gr*CC + j*2);
    uint32_t hi, lo; bsplit(v.x, v.y, hi, lo);
    sm[AHI + row*PITCH + j] = hi;
    sm[ALO + row*PITCH + j] = lo;
  }
  CP_WAIT(0);
  __syncthreads();

  uint32_t a_toff = (uint32_t)(((mw*32 + (lane&15))*PITCH + (lane>>4)*4))*4;
  uint32_t b_toff = (uint32_t)(((nw*32 + (lane&7) + (lane>>4)*8)*PITCH + ((lane>>3)&1)*4))*4;

  float acc[2][4][4];
  #pragma unroll
  for (int a=0;a<2;a++)
    #pragma unroll
    for (int b=0;b<4;b++)
      #pragma unroll
      for (int c=0;c<4;c++) acc[a][b][c]=0.f;

  mma_core(sb + (uint32_t)AHI*4 + a_toff, sb + (uint32_t)ALO*4 + a_toff,
           sb + (uint32_t)B0HI*4 + b_toff, sb + (uint32_t)B0LO*4 + b_toff, acc);

  float* reds = (float*)(sm + RED0);          // 512 floats
  float* redq = (float*)(sm + RED0 + 512);    // 512 floats

  float2 bb[4];
  #pragma unroll
  for (int nt = 0; nt < 4; nt++) bb[nt] = *(const float2*)(bias + nw*32 + nt*8 + tq*2);

  #pragma unroll
  for (int mt = 0; mt < 2; mt++){
    #pragma unroll
    for (int h = 0; h < 2; h++){
      int lr = mw*32 + mt*16 + tg + h*8;
      int grow = row0 + lr;
      float dg = 0.f, idg = 0.f;
      if (grow < NN){ dg = (float)deg[grow]; idg = (float)indeg[grow]; }
      float s = 0.f;
      #pragma unroll
      for (int nt = 0; nt < 4; nt++){
        int col = nw*32 + nt*8 + tq*2;
        float2 xr = make_float2(0.f, 0.f);
        if (grow < NN) xr = *(const float2*)(xres + (size_t)grow*CC + col);
        float v0 = acc[mt][nt][h*2+0] + bb[nt].x*idg + dg + xr.x;
        float v1 = acc[mt][nt][h*2+1] + bb[nt].y*idg + dg + xr.y;
        acc[mt][nt][h*2+0] = v0;
        acc[mt][nt][h*2+1] = v1;
        s += v0 + v1;
      }
      s += __shfl_xor_sync(0xffffffffu, s, 1);
      s += __shfl_xor_sync(0xffffffffu, s, 2);
      if (tq == 0) reds[lr*4 + nw] = s;
    }
  }
  __syncthreads();

  float mu[2][2];
  #pragma unroll
  for (int mt = 0; mt < 2; mt++)
    #pragma unroll
    for (int h = 0; h < 2; h++){
      int lr = mw*32 + mt*16 + tg + h*8;
      mu[mt][h] = (reds[lr*4] + reds[lr*4+1] + reds[lr*4+2] + reds[lr*4+3]) * (1.f/128.f);
    }

  #pragma unroll
  for (int mt = 0; mt < 2; mt++){
    #pragma unroll
    for (int h = 0; h < 2; h++){
      int lr = mw*32 + mt*16 + tg + h*8;
      float q = 0.f;
      #pragma unroll
      for (int nt = 0; nt < 4; nt++){
        float d0 = acc[mt][nt][h*2+0] - mu[mt][h];
        float d1 = acc[mt][nt][h*2+1] - mu[mt][h];
        q += d0*d0 + d1*d1;
      }
      q += __shfl_xor_sync(0xffffffffu, q, 1);
      q += __shfl_xor_sync(0xffffffffu, q, 2);
      if (tq == 0) redq[lr*4 + nw] = q;
    }
  }
  __syncthreads();

  #pragma unroll
  for (int mt = 0; mt < 2; mt++){
    #pragma unroll
    for (int h = 0; h < 2; h++){
      int lr = mw*32 + mt*16 + tg + h*8;
      int grow = row0 + lr;
      if (grow >= NN) continue;
      float var = (redq[lr*4] + redq[lr*4+1] + redq[lr*4+2] + redq[lr*4+3]) * (1.f/128.f);
      float rs = rsqrtf(var + 1e-5f);
      float m = mu[mt][h];
      #pragma unroll
      for (int nt = 0; nt < 4; nt++){
        int col = nw*32 + nt*8 + tq*2;
        *(float2*)(o + (size_t)grow*CC + col) =
          make_float2((acc[mt][nt][h*2+0]-m)*rs, (acc[mt][nt][h*2+1]-m)*rs);
      }
    }
  }
}

// ---------------- launch ----------------
extern "C" void kernel_launch(void* const* d_in, const int* in_sizes, int n_in,
                              void* d_out, int out_size){
  const float* x_user=(const float*)d_in[0];
  const float* x_item=(const float*)d_in[1];
  const float* t_user=(const float*)d_in[2];
  const float* t_item=(const float*)d_in[3];
  const int*   eui  =(const int*)  d_in[4];
  const int*   eiu  =(const int*)  d_in[5];
  const float* Wq=(const float*)d_in[6];  const float* bq=(const float*)d_in[7];
  const float* Wk=(const float*)d_in[8];  const float* bk=(const float*)d_in[9];
  const float* Wv=(const float*)d_in[10]; const float* bv=(const float*)d_in[11];
  const float* Wo=(const float*)d_in[12]; const float* bo=(const float*)d_in[13];
  const float* hb=(const float*)d_in[14];
  const float* tb=(const float*)d_in[15];
  const float* traw=(const float*)d_in[16];
  const float* gm=(const float*)d_in[17];
  const float* dr=(const float*)d_in[18];
  float* out=(float*)d_out;

  float *Qu,*Ku,*Vu,*Qi,*Ki,*Vi,*aggu,*aggi;
  int *degu,*degi,*idgu,*idgi;
  cudaGetSymbolAddress((void**)&Qu, g_Qu);
  cudaGetSymbolAddress((void**)&Ku, g_Ku);
  cudaGetSymbolAddress((void**)&Vu, g_Vu);
  cudaGetSymbolAddress((void**)&Qi, g_Qi);
  cudaGetSymbolAddress((void**)&Ki, g_Ki);
  cudaGetSymbolAddress((void**)&Vi, g_Vi);
  cudaGetSymbolAddress((void**)&aggu, g_agg_u);
  cudaGetSymbolAddress((void**)&aggi, g_agg_i);
  cudaGetSymbolAddress((void**)&degu, g_deg_u);
  cudaGetSymbolAddress((void**)&degi, g_deg_i);
  cudaGetSymbolAddress((void**)&idgu, g_indeg_u);
  cudaGetSymbolAddress((void**)&idgi, g_indeg_i);

  cudaFuncSetAttribute(k_qkv3,   cudaFuncAttributeMaxDynamicSharedMemorySize, QKV_SMEMB);
  cudaFuncSetAttribute(k_out_mma,cudaFuncAttributeMaxDynamicSharedMemorySize, OUT_SMEMB);
  cudaFuncSetAttribute(k_scan2,  cudaFuncAttributeMaxDynamicSharedMemorySize, SCAN_SMEMB);

  // Fork a second stream inside graph capture: chain A (edge preprocessing)
  // overlaps with chain B (weight split + QKV GEMMs).
  cudaStream_t s2;
  cudaStreamCreateWithFlags(&s2, cudaStreamNonBlocking);
  cudaEvent_t eFork, eJoin;
  cudaEventCreateWithFlags(&eFork, cudaEventDisableTiming);
  cudaEventCreateWithFlags(&eJoin, cudaEventDisableTiming);

  cudaEventRecord(eFork, 0);
  cudaStreamWaitEvent(s2, eFork, 0);

  // chain A on s2: hash tables + degrees + CSR
  k_init<<<1024,256,0,s2>>>();
  k_build<<<(2*EE+255)/256,256,0,s2>>>(eui, eiu);
  k_scan2<<<2,1024,SCAN_SMEMB,s2>>>();
  k_scatter<<<(2*EE+255)/256,256,0,s2>>>(eui, eiu);
  cudaEventRecord(eJoin, s2);

  // chain B on capture stream: weight planes + QKV projections
  k_wsplit<<<dim3(32,4),256>>>(Wq, Wk, Wv, Wo);
  k_qkv3<<<dim3(NBLK,2),512,QKV_SMEMB>>>(x_user, x_item, Qu,Ku,Vu, Qi,Ki,Vi, bq,bk,bv);

  // join: aggregation needs both chains
  cudaStreamWaitEvent(0, eJoin, 0);

  // both relations in one launch (r = blockIdx.y: 0 = user->item, 1 = item->user)
  k_agg2<<<dim3((NN+7)/8,2),256>>>(Qi, Ku, Vu, Qu, Ki, Vi, t_user, t_item,
                                   hb, tb, traw, gm, dr);

  k_out_mma<<<dim3(NBLK,2),512,OUT_SMEMB>>>(aggu, aggi, bo,
                                            idgu, idgi, degu, degi,
                                            x_user, x_item, out);
}